// round 3
// baseline (speedup 1.0000x reference)
#include <cuda_runtime.h>
#include <math.h>

#define NB   16
#define NCH  22
#define NT   1000
#define NEXP 300
#define NF   150
#define NS   100
#define PIT  101
#define ROWS_PER 30

__device__ float d_Meff[3 * NF * NCH];
__device__ float d_H[(size_t)NB * 450 * NT];
__device__ float d_SC[(size_t)NB * NS * NT];
__device__ float d_covp[(size_t)NB * 4 * NS * NS];
__device__ float d_P[(size_t)NB * NS * NS];

struct BP  { const float *w5, *g1, *b1, *g2, *b2; int K; };
struct BPs { BP p[3]; };
struct PrepP  { const float *w1, *w2, *w3, *w4; };
struct PrepPs { PrepP p[3]; };

// ---------- reductions (blockDim == 256) ----------
__device__ __forceinline__ float blk_reduce(float v, float* red) {
    int lane = threadIdx.x & 31, wid = threadIdx.x >> 5;
#pragma unroll
    for (int o = 16; o; o >>= 1) v += __shfl_xor_sync(0xffffffffu, v, o);
    if (lane == 0) red[wid] = v;
    __syncthreads();
    if (wid == 0) {
        float x = (lane < 8) ? red[lane] : 0.0f;
#pragma unroll
        for (int o = 4; o; o >>= 1) x += __shfl_xor_sync(0xffffffffu, x, o);
        if (lane == 0) red[0] = x;
    }
    __syncthreads();
    float r = red[0];
    __syncthreads();
    return r;
}

__device__ __forceinline__ float2 blk_reduce2(float a, float b, float* red) {
    int lane = threadIdx.x & 31, wid = threadIdx.x >> 5;
#pragma unroll
    for (int o = 16; o; o >>= 1) {
        a += __shfl_xor_sync(0xffffffffu, a, o);
        b += __shfl_xor_sync(0xffffffffu, b, o);
    }
    if (lane == 0) { red[wid] = a; red[32 + wid] = b; }
    __syncthreads();
    if (wid == 0) {
        float x = (lane < 8) ? red[lane] : 0.0f;
        float y = (lane < 8) ? red[32 + lane] : 0.0f;
#pragma unroll
        for (int o = 4; o; o >>= 1) {
            x += __shfl_xor_sync(0xffffffffu, x, o);
            y += __shfl_xor_sync(0xffffffffu, y, o);
        }
        if (lane == 0) { red[0] = x; red[32] = y; }
    }
    __syncthreads();
    float2 r = make_float2(red[0], red[32]);
    __syncthreads();
    return r;
}

// ---------- K1: fold block weights into Meff (150x22) ----------
__global__ void k_prep(PrepPs ps) {
    int blk = blockIdx.x;
    PrepP w = ps.p[blk];
    __shared__ float w3s[NEXP * NCH];
    int tid = threadIdx.x;
    for (int g = tid; g < NEXP; g += 256) {
        float s = 0.f;
        for (int c = 0; c < NCH; c++) { float v = w.w3[g * NCH + c]; s += v * v; }
        float n = sqrtf(s);
        float sc = fminf(1.0f, 1.0f / (n + 1e-12f)) * w.w2[g];
        for (int c = 0; c < NCH; c++) w3s[g * NCH + c] = w.w3[g * NCH + c] * sc;
    }
    __syncthreads();
    float w10 = w.w1[0], w11 = w.w1[1], w12 = w.w1[2];
    for (int o = tid; o < NF; o += 256) {
        float m[NCH];
#pragma unroll
        for (int c = 0; c < NCH; c++) m[c] = 0.f;
        for (int g = 0; g < NEXP; g++) {
            float w4v = w.w4[o * NEXP + g];
#pragma unroll
            for (int c = 0; c < NCH; c++) m[c] += w4v * w3s[g * NCH + c];
        }
        // electrode conv fold: Meff[o,c] = w1[0]*A[o,c+1] + w1[1]*A[o,c] + w1[2]*A[o,c-1]
        for (int c = 0; c < NCH; c++) {
            float am = (c > 0) ? m[c - 1] : 0.f;
            float ap = (c < NCH - 1) ? m[c + 1] : 0.f;
            d_Meff[(blk * NF + o) * NCH + c] = w10 * ap + w11 * m[c] + w12 * am;
        }
    }
}

// ---------- K2: per-block  Meff@x -> LN -> depthwise temporal conv -> LN ----------
__global__ void k_block(const float* __restrict__ x, BPs bps) {
    int b = blockIdx.x, blk = blockIdx.y, rc = blockIdx.z;
    BP bp = bps.p[blk];
    int K = bp.K, Kh = K / 2;
    extern __shared__ float sm[];
    float* xsh  = sm;                       // 22*1000
    float* rbuf = xsh + NCH * NT;           // 1008
    float* meff = rbuf + 1008;              // 30*22
    float* w5s  = meff + ROWS_PER * NCH;    // 30*75 (max)
    float* g1s  = w5s + ROWS_PER * 75;
    float* b1s  = g1s + NT;
    float* g2s  = b1s + NT;
    float* b2s  = g2s + NT;
    __shared__ float red[64];
    int tid = threadIdx.x;
    int o0 = rc * ROWS_PER;

    for (int i = tid; i < NCH * NT; i += 256) xsh[i] = x[(size_t)b * NCH * NT + i];
    for (int i = tid; i < ROWS_PER * NCH; i += 256) meff[i] = d_Meff[(blk * NF + o0) * NCH + i];
    for (int i = tid; i < ROWS_PER * K; i += 256) w5s[i] = bp.w5[o0 * K + i];
    for (int i = tid; i < NT; i += 256) {
        g1s[i] = bp.g1[i]; b1s[i] = bp.b1[i];
        g2s[i] = bp.g2[i]; b2s[i] = bp.b2[i];
    }
    __syncthreads();

    for (int oo = 0; oo < ROWS_PER; oo++) {
        float h[4]; float s1 = 0.f, s2 = 0.f;
#pragma unroll
        for (int j = 0; j < 4; j++) {
            int t = tid + 256 * j; float a = 0.f;
            if (t < NT) {
#pragma unroll
                for (int c = 0; c < NCH; c++) a += meff[oo * NCH + c] * xsh[c * NT + t];
                s1 += a; s2 += a * a;
            }
            h[j] = a;
        }
        float2 r = blk_reduce2(s1, s2, red);
        float mean = r.x * (1.0f / NT);
        float rstd = rsqrtf(r.y * (1.0f / NT) - mean * mean + 1e-5f);
#pragma unroll
        for (int j = 0; j < 4; j++) {
            int t = tid + 256 * j;
            if (t < NT) rbuf[t] = (h[j] - mean) * rstd * g1s[t] + b1s[t];
        }
        __syncthreads();
        float cv[4]; s1 = 0.f; s2 = 0.f;
#pragma unroll
        for (int j = 0; j < 4; j++) {
            int t = tid + 256 * j; float a = 0.f;
            if (t < NT) {
                for (int k = 0; k < K; k++) {
                    int tt = t + k - Kh;
                    if (tt >= 0 && tt < NT) a += w5s[oo * K + k] * rbuf[tt];
                }
                s1 += a; s2 += a * a;
            }
            cv[j] = a;
        }
        float2 r2 = blk_reduce2(s1, s2, red);  // syncs inside also protect rbuf reuse
        float m2 = r2.x * (1.0f / NT);
        float rs2 = rsqrtf(r2.y * (1.0f / NT) - m2 * m2 + 1e-5f);
        float* outp = d_H + ((size_t)(b * 450 + blk * NF + o0 + oo)) * NT;
#pragma unroll
        for (int j = 0; j < 4; j++) {
            int t = tid + 256 * j;
            if (t < NT) outp[t] = (cv[j] - m2) * rs2 * g2s[t] + b2s[t];
        }
    }
}

// ---------- K3: spatial conv 450->100 + center over time ----------
__global__ void k_sconv(const float* __restrict__ wsc) {
    int b = blockIdx.x, s0 = blockIdx.y * 4;
    __shared__ float ws[4 * 450];
    __shared__ float red[64];
    int tid = threadIdx.x;
    for (int i = tid; i < 4 * 450; i += 256) ws[i] = wsc[s0 * 450 + i];
    __syncthreads();
    const float* Hb = d_H + (size_t)b * 450 * NT;
    float acc[4][4];
#pragma unroll
    for (int r = 0; r < 4; r++)
#pragma unroll
        for (int j = 0; j < 4; j++) acc[r][j] = 0.f;
    for (int i = 0; i < 450; i++) {
        const float* hp = Hb + (size_t)i * NT;
        float hv[4];
#pragma unroll
        for (int j = 0; j < 4; j++) {
            int t = tid + 256 * j;
            hv[j] = (t < NT) ? hp[t] : 0.f;
        }
#pragma unroll
        for (int r = 0; r < 4; r++) {
            float w = ws[r * 450 + i];
#pragma unroll
            for (int j = 0; j < 4; j++) acc[r][j] += w * hv[j];
        }
    }
#pragma unroll
    for (int r = 0; r < 4; r++) {
        float s = 0.f;
#pragma unroll
        for (int j = 0; j < 4; j++) { int t = tid + 256 * j; if (t < NT) s += acc[r][j]; }
        s = blk_reduce(s, red);
        float mean = s * (1.0f / NT);
        float* op = d_SC + ((size_t)(b * NS + s0 + r)) * NT;
#pragma unroll
        for (int j = 0; j < 4; j++) {
            int t = tid + 256 * j;
            if (t < NT) op[t] = acc[r][j] - mean;
        }
    }
}

// ---------- K4: partial covariance (register-tiled 7x7 outer product) ----------
__global__ void k_covp() {
    int b = blockIdx.x, ch = blockIdx.y;
    __shared__ float sh[NS * 53];
    int tid = threadIdx.x, tx = tid & 15, ty = tid >> 4;
    float acc[7][7];
#pragma unroll
    for (int a = 0; a < 7; a++)
#pragma unroll
        for (int c = 0; c < 7; c++) acc[a][c] = 0.f;
    int tbase0 = ch * 250;
    for (int cc = 0; cc < 5; cc++) {
        int tb = tbase0 + cc * 50;
        __syncthreads();
        for (int idx = tid; idx < NS * 50; idx += 256) {
            int i = idx / 50, tt = idx - i * 50;
            sh[i * 53 + tt] = d_SC[((size_t)(b * NS + i)) * NT + tb + tt];
        }
        __syncthreads();
        for (int tt = 0; tt < 50; tt++) {
            float ai[7], aj[7];
#pragma unroll
            for (int a = 0; a < 7; a++) { int i = ty + 16 * a; ai[a] = (i < NS) ? sh[i * 53 + tt] : 0.f; }
#pragma unroll
            for (int c = 0; c < 7; c++) { int j = tx + 16 * c; aj[c] = (j < NS) ? sh[j * 53 + tt] : 0.f; }
#pragma unroll
            for (int a = 0; a < 7; a++)
#pragma unroll
                for (int c = 0; c < 7; c++) acc[a][c] += ai[a] * aj[c];
        }
    }
#pragma unroll
    for (int a = 0; a < 7; a++)
#pragma unroll
        for (int c = 0; c < 7; c++) {
            int i = ty + 16 * a, j = tx + 16 * c;
            if (i < NS && j < NS)
                d_covp[((size_t)(b * 4 + ch) * NS + i) * NS + j] = acc[a][c];
        }
}

// ---------- K5: cov reduce + ridge + P = W cov W^T ----------
__global__ void k_affine(const float* __restrict__ waff) {
    int b = blockIdx.x;
    extern __shared__ float sm[];
    float* covs = sm;
    float* Ws = covs + NS * PIT;
    float* Ts = Ws + NS * PIT;
    int tid = threadIdx.x, tx = tid & 15, ty = tid >> 4;
    for (int idx = tid; idx < NS * NS; idx += 256) {
        int i = idx / NS, j = idx - i * NS;
        const float* pp = d_covp + (size_t)b * 4 * NS * NS + idx;
        float v = (pp[0] + pp[NS * NS] + pp[2 * NS * NS] + pp[3 * NS * NS]) * (1.0f / 999.0f);
        if (i == j) v += 1e-4f;
        covs[i * PIT + j] = v;
        Ws[i * PIT + j] = waff[idx];
    }
    __syncthreads();
    float acc[7][7];
#pragma unroll
    for (int a = 0; a < 7; a++)
#pragma unroll
        for (int c = 0; c < 7; c++) acc[a][c] = 0.f;
    for (int k = 0; k < NS; k++) {
        float wa[7], cb[7];
#pragma unroll
        for (int a = 0; a < 7; a++) { int i = ty + 16 * a; wa[a] = (i < NS) ? Ws[i * PIT + k] : 0.f; }
#pragma unroll
        for (int c = 0; c < 7; c++) { int j = tx + 16 * c; cb[c] = (j < NS) ? covs[k * PIT + j] : 0.f; }
#pragma unroll
        for (int a = 0; a < 7; a++)
#pragma unroll
            for (int c = 0; c < 7; c++) acc[a][c] += wa[a] * cb[c];
    }
#pragma unroll
    for (int a = 0; a < 7; a++)
#pragma unroll
        for (int c = 0; c < 7; c++) {
            int i = ty + 16 * a, j = tx + 16 * c;
            if (i < NS && j < NS) Ts[i * PIT + j] = acc[a][c];
        }
    __syncthreads();
#pragma unroll
    for (int a = 0; a < 7; a++)
#pragma unroll
        for (int c = 0; c < 7; c++) acc[a][c] = 0.f;
    for (int k = 0; k < NS; k++) {
        float ta[7], wb[7];
#pragma unroll
        for (int a = 0; a < 7; a++) { int i = ty + 16 * a; ta[a] = (i < NS) ? Ts[i * PIT + k] : 0.f; }
#pragma unroll
        for (int c = 0; c < 7; c++) { int j = tx + 16 * c; wb[c] = (j < NS) ? Ws[j * PIT + k] : 0.f; }
#pragma unroll
        for (int a = 0; a < 7; a++)
#pragma unroll
            for (int c = 0; c < 7; c++) acc[a][c] += ta[a] * wb[c];
    }
#pragma unroll
    for (int a = 0; a < 7; a++)
#pragma unroll
        for (int c = 0; c < 7; c++) {
            int i = ty + 16 * a, j = tx + 16 * c;
            if (i < NS && j < NS) d_P[(size_t)b * NS * NS + i * NS + j] = acc[a][c];
        }
}

// ---------- K6: Jacobi eigh + logm + triu-vec + FC ----------
__global__ void k_eig(const float* __restrict__ wfc, const float* __restrict__ bfc,
                      float* __restrict__ out) {
    int b = blockIdx.x;
    extern __shared__ float sm[];
    float* As = sm;
    float* Vs = As + NS * PIT;
    __shared__ float cc[50], ssn[50];
    __shared__ int ppn[50], qqn[50];
    __shared__ float red[64];
    __shared__ float llog[NS];
    int tid = threadIdx.x;
    const float* Pb = d_P + (size_t)b * NS * NS;
    for (int idx = tid; idx < NS * NS; idx += 256) {
        int i = idx / NS, j = idx - i * NS;
        As[i * PIT + j] = 0.5f * (Pb[i * NS + j] + Pb[j * NS + i]);
        Vs[i * PIT + j] = (i == j) ? 1.0f : 0.0f;
    }
    __syncthreads();

    for (int sweep = 0; sweep < 18; sweep++) {
        float o2 = 0.f, d2 = 0.f;
        for (int idx = tid; idx < NS * NS; idx += 256) {
            int i = idx / NS, j = idx - i * NS;
            float v = As[i * PIT + j];
            if (i == j) d2 += v * v; else o2 += v * v;
        }
        float2 r = blk_reduce2(o2, d2, red);
        if (r.x <= 1e-11f * r.y) break;

        for (int rnd = 0; rnd < 99; rnd++) {
            if (tid < 50) {
                int p, q;
                if (tid == 0) { p = rnd % 99; q = 99; }
                else { p = (rnd + tid) % 99; q = (rnd + 99 - tid) % 99; }
                float apq = As[p * PIT + q];
                float app = As[p * PIT + p], aqq = As[q * PIT + q];
                float c = 1.0f, s = 0.0f;
                if (fabsf(apq) > 1e-9f * sqrtf(fabsf(app * aqq)) + 1e-38f) {
                    float tau = (aqq - app) / (2.0f * apq);
                    float t = 1.0f / (fabsf(tau) + sqrtf(1.0f + tau * tau));
                    if (tau < 0.f) t = -t;
                    c = 1.0f / sqrtf(1.0f + t * t);
                    s = t * c;
                }
                cc[tid] = c; ssn[tid] = s; ppn[tid] = p; qqn[tid] = q;
            }
            __syncthreads();
            // column phase on A and V
            for (int idx = tid; idx < 5000; idx += 256) {
                int k = idx / 100, i = idx - k * 100;
                float s = ssn[k];
                if (s != 0.0f) {
                    float c = cc[k]; int p = ppn[k], q = qqn[k];
                    float xp = As[i * PIT + p], xq = As[i * PIT + q];
                    As[i * PIT + p] = c * xp - s * xq;
                    As[i * PIT + q] = s * xp + c * xq;
                    xp = Vs[i * PIT + p]; xq = Vs[i * PIT + q];
                    Vs[i * PIT + p] = c * xp - s * xq;
                    Vs[i * PIT + q] = s * xp + c * xq;
                }
            }
            __syncthreads();
            // row phase on A
            for (int idx = tid; idx < 5000; idx += 256) {
                int k = idx / 100, j = idx - k * 100;
                float s = ssn[k];
                if (s != 0.0f) {
                    float c = cc[k]; int p = ppn[k], q = qqn[k];
                    float xp = As[p * PIT + j], xq = As[q * PIT + j];
                    As[p * PIT + j] = c * xp - s * xq;
                    As[q * PIT + j] = s * xp + c * xq;
                }
            }
            __syncthreads();
        }
    }

    // log eigenvalues, build Vl = V * diag(log lam) into As
    if (tid < NS) llog[tid] = logf(fmaxf(As[tid * PIT + tid], 1e-6f));
    __syncthreads();
    for (int idx = tid; idx < NS * NS; idx += 256) {
        int i = idx / NS, k = idx - i * NS;
        As[i * PIT + k] = Vs[i * PIT + k] * llog[k];
    }
    __syncthreads();

    float l0 = 0.f, l1 = 0.f, l2 = 0.f, l3 = 0.f;
    float* flat = out + 64 + (size_t)b * 5050;
    for (int idx = tid; idx < 5050; idx += 256) {
        int i = (int)((201.0f - sqrtf(201.0f * 201.0f - 8.0f * (float)idx)) * 0.5f);
        if (i < 0) i = 0; if (i > 99) i = 99;
        while (i > 0 && i * (201 - i) / 2 > idx) i--;
        while (i < 99 && (i + 1) * (200 - i) / 2 <= idx) i++;
        int j = i + (idx - i * (201 - i) / 2);
        float a = 0.f;
        for (int k = 0; k < NS; k++) a += As[i * PIT + k] * Vs[j * PIT + k];
        float v = a * ((i == j) ? 1.0f : 1.41421356237309515f);
        flat[idx] = v;
        l0 += v * wfc[idx];
        l1 += v * wfc[5050 + idx];
        l2 += v * wfc[2 * 5050 + idx];
        l3 += v * wfc[3 * 5050 + idx];
    }
    l0 = blk_reduce(l0, red);
    l1 = blk_reduce(l1, red);
    l2 = blk_reduce(l2, red);
    l3 = blk_reduce(l3, red);
    if (tid == 0) {
        out[b * 4 + 0] = l0 + bfc[0];
        out[b * 4 + 1] = l1 + bfc[1];
        out[b * 4 + 2] = l2 + bfc[2];
        out[b * 4 + 3] = l3 + bfc[3];
    }
}

// ---------- launch ----------
extern "C" void kernel_launch(void* const* d_in, const int* in_sizes, int n_in,
                              void* d_out, int out_size) {
    const float* x = (const float*)d_in[0];
    PrepPs pps; BPs bps;
    int Ks[3] = {15, 75, 55};
    for (int bi = 0; bi < 3; bi++) {
        int base = 1 + bi * 9;
        pps.p[bi].w1 = (const float*)d_in[base + 0];
        pps.p[bi].w2 = (const float*)d_in[base + 1];
        pps.p[bi].w3 = (const float*)d_in[base + 2];
        pps.p[bi].w4 = (const float*)d_in[base + 3];
        bps.p[bi].g1 = (const float*)d_in[base + 4];
        bps.p[bi].b1 = (const float*)d_in[base + 5];
        bps.p[bi].w5 = (const float*)d_in[base + 6];
        bps.p[bi].g2 = (const float*)d_in[base + 7];
        bps.p[bi].b2 = (const float*)d_in[base + 8];
        bps.p[bi].K = Ks[bi];
    }
    const float* wsc  = (const float*)d_in[28];
    const float* waff = (const float*)d_in[29];
    const float* wfc  = (const float*)d_in[30];
    const float* bfc  = (const float*)d_in[31];

    const int SMEM_BLOCK = (NCH * NT + 1008 + ROWS_PER * NCH + ROWS_PER * 75 + 4 * NT) * 4;
    const int SMEM_AFF = 3 * NS * PIT * 4;
    const int SMEM_EIG = 2 * NS * PIT * 4;
    cudaFuncSetAttribute(k_block, cudaFuncAttributeMaxDynamicSharedMemorySize, SMEM_BLOCK);
    cudaFuncSetAttribute(k_affine, cudaFuncAttributeMaxDynamicSharedMemorySize, SMEM_AFF);
    cudaFuncSetAttribute(k_eig, cudaFuncAttributeMaxDynamicSharedMemorySize, SMEM_EIG);

    k_prep<<<3, 256>>>(pps);
    k_block<<<dim3(NB, 3, 5), 256, SMEM_BLOCK>>>(x, bps);
    k_sconv<<<dim3(NB, 25), 256>>>(wsc);
    k_covp<<<dim3(NB, 4), 256>>>();
    k_affine<<<NB, 256, SMEM_AFF>>>(waff);
    k_eig<<<NB, 256, SMEM_EIG>>>(wfc, bfc, (float*)d_out);
}

// round 4
// speedup vs baseline: 2.0141x; 2.0141x over previous
#include <cuda_runtime.h>
#include <math.h>

#define NB   16
#define NCH  22
#define NT   1000
#define NEXP 300
#define NF   150
#define NS   100
#define PIT  101
#define ROWS_PER 30

__device__ float d_Meff[3 * NF * NCH];
__device__ float d_H[(size_t)NB * 450 * NT];
__device__ float d_SC[(size_t)NB * NS * NT];
__device__ float d_covp[(size_t)NB * 8 * NS * NS];
__device__ float d_P[(size_t)NB * NS * NS];

struct BP  { const float *w5, *g1, *b1, *g2, *b2; };
struct BPs { BP p[3]; };
struct PrepP  { const float *w1, *w2, *w3, *w4; };
struct PrepPs { PrepP p[3]; };

// ---------- reductions (NW = warps per block) ----------
template<int NW>
__device__ __forceinline__ float blk_reduce(float v, float* red) {
    int lane = threadIdx.x & 31, wid = threadIdx.x >> 5;
#pragma unroll
    for (int o = 16; o; o >>= 1) v += __shfl_xor_sync(0xffffffffu, v, o);
    if (lane == 0) red[wid] = v;
    __syncthreads();
    if (wid == 0) {
        float x = (lane < NW) ? red[lane] : 0.0f;
#pragma unroll
        for (int o = NW > 16 ? 16 : NW / 2; o; o >>= 1) x += __shfl_xor_sync(0xffffffffu, x, o);
        if (lane == 0) red[0] = x;
    }
    __syncthreads();
    float r = red[0];
    __syncthreads();
    return r;
}

template<int NW>
__device__ __forceinline__ float2 blk_reduce2(float a, float b, float* red) {
    int lane = threadIdx.x & 31, wid = threadIdx.x >> 5;
#pragma unroll
    for (int o = 16; o; o >>= 1) {
        a += __shfl_xor_sync(0xffffffffu, a, o);
        b += __shfl_xor_sync(0xffffffffu, b, o);
    }
    if (lane == 0) { red[wid] = a; red[32 + wid] = b; }
    __syncthreads();
    if (wid == 0) {
        float x = (lane < NW) ? red[lane] : 0.0f;
        float y = (lane < NW) ? red[32 + lane] : 0.0f;
#pragma unroll
        for (int o = NW > 16 ? 16 : NW / 2; o; o >>= 1) {
            x += __shfl_xor_sync(0xffffffffu, x, o);
            y += __shfl_xor_sync(0xffffffffu, y, o);
        }
        if (lane == 0) { red[0] = x; red[32] = y; }
    }
    __syncthreads();
    float2 r = make_float2(red[0], red[32]);
    __syncthreads();
    return r;
}

// ---------- K1: fold block weights into Meff (150x22) ----------
__global__ void k_prep(PrepPs ps) {
    int blk = blockIdx.x;
    PrepP w = ps.p[blk];
    __shared__ float w3s[NEXP * NCH];
    int tid = threadIdx.x;
    for (int g = tid; g < NEXP; g += 256) {
        float s = 0.f;
        for (int c = 0; c < NCH; c++) { float v = w.w3[g * NCH + c]; s += v * v; }
        float n = sqrtf(s);
        float sc = fminf(1.0f, 1.0f / (n + 1e-12f)) * w.w2[g];
        for (int c = 0; c < NCH; c++) w3s[g * NCH + c] = w.w3[g * NCH + c] * sc;
    }
    __syncthreads();
    float w10 = w.w1[0], w11 = w.w1[1], w12 = w.w1[2];
    for (int o = tid; o < NF; o += 256) {
        float m[NCH];
#pragma unroll
        for (int c = 0; c < NCH; c++) m[c] = 0.f;
        for (int g = 0; g < NEXP; g++) {
            float w4v = w.w4[o * NEXP + g];
#pragma unroll
            for (int c = 0; c < NCH; c++) m[c] += w4v * w3s[g * NCH + c];
        }
        for (int c = 0; c < NCH; c++) {
            float am = (c > 0) ? m[c - 1] : 0.f;
            float ap = (c < NCH - 1) ? m[c + 1] : 0.f;
            d_Meff[(blk * NF + o) * NCH + c] = w10 * ap + w11 * m[c] + w12 * am;
        }
    }
}

// ---------- K2: per-block Meff@x -> LN -> depthwise temporal conv -> LN ----------
template<int K>
__device__ __forceinline__ void block_impl(const float* __restrict__ x, BP bp, int blk,
                                           int b, int rc, float* sm, float* red) {
    const int Kh = K / 2;
    float* xsh  = sm;
    float* rbuf = xsh + NCH * NT;
    float* meff = rbuf + 1008;
    float* w5s  = meff + ROWS_PER * NCH;
    float* g1s  = w5s + ROWS_PER * 75;
    float* b1s  = g1s + NT;
    float* g2s  = b1s + NT;
    float* b2s  = g2s + NT;
    int tid = threadIdx.x;
    int o0 = rc * ROWS_PER;

    for (int i = tid; i < NCH * NT; i += 256) xsh[i] = x[(size_t)b * NCH * NT + i];
    for (int i = tid; i < ROWS_PER * NCH; i += 256) meff[i] = d_Meff[(blk * NF + o0) * NCH + i];
    for (int i = tid; i < ROWS_PER * K; i += 256) w5s[i] = bp.w5[o0 * K + i];
    for (int i = tid; i < NT; i += 256) {
        g1s[i] = bp.g1[i]; b1s[i] = bp.b1[i];
        g2s[i] = bp.g2[i]; b2s[i] = bp.b2[i];
    }
    __syncthreads();

    for (int oo = 0; oo < ROWS_PER; oo++) {
        float h[4]; float s1 = 0.f, s2 = 0.f;
#pragma unroll
        for (int j = 0; j < 4; j++) {
            int t = tid + 256 * j; float a = 0.f;
            if (t < NT) {
#pragma unroll
                for (int c = 0; c < NCH; c++) a += meff[oo * NCH + c] * xsh[c * NT + t];
                s1 += a; s2 += a * a;
            }
            h[j] = a;
        }
        float2 r = blk_reduce2<8>(s1, s2, red);
        float mean = r.x * (1.0f / NT);
        float rstd = rsqrtf(r.y * (1.0f / NT) - mean * mean + 1e-5f);
#pragma unroll
        for (int j = 0; j < 4; j++) {
            int t = tid + 256 * j;
            if (t < NT) rbuf[t] = (h[j] - mean) * rstd * g1s[t] + b1s[t];
        }
        __syncthreads();
        float cv[4]; s1 = 0.f; s2 = 0.f;
#pragma unroll
        for (int j = 0; j < 4; j++) {
            int t = tid + 256 * j; float a = 0.f;
            if (t < NT) {
#pragma unroll
                for (int k = 0; k < K; k++) {
                    int tt = t + k - Kh;
                    if (tt >= 0 && tt < NT) a += w5s[oo * K + k] * rbuf[tt];
                }
                s1 += a; s2 += a * a;
            }
            cv[j] = a;
        }
        float2 r2 = blk_reduce2<8>(s1, s2, red);
        float m2 = r2.x * (1.0f / NT);
        float rs2 = rsqrtf(r2.y * (1.0f / NT) - m2 * m2 + 1e-5f);
        float* outp = d_H + ((size_t)(b * 450 + blk * NF + o0 + oo)) * NT;
#pragma unroll
        for (int j = 0; j < 4; j++) {
            int t = tid + 256 * j;
            if (t < NT) outp[t] = (cv[j] - m2) * rs2 * g2s[t] + b2s[t];
        }
    }
}

__global__ void k_block(const float* __restrict__ x, BPs bps) {
    int b = blockIdx.x, blk = blockIdx.y, rc = blockIdx.z;
    extern __shared__ float sm[];
    __shared__ float red[64];
    if (blk == 0)      block_impl<15>(x, bps.p[0], 0, b, rc, sm, red);
    else if (blk == 1) block_impl<75>(x, bps.p[1], 1, b, rc, sm, red);
    else               block_impl<55>(x, bps.p[2], 2, b, rc, sm, red);
}

// ---------- K3: spatial conv 450->100 + center over time ----------
__global__ void k_sconv(const float* __restrict__ wsc) {
    int b = blockIdx.x, s0 = blockIdx.y * 4;
    __shared__ float ws[4 * 450];
    __shared__ float red[64];
    int tid = threadIdx.x;
    for (int i = tid; i < 4 * 450; i += 256) ws[i] = wsc[s0 * 450 + i];
    __syncthreads();
    const float* Hb = d_H + (size_t)b * 450 * NT;
    float acc[4][4];
#pragma unroll
    for (int r = 0; r < 4; r++)
#pragma unroll
        for (int j = 0; j < 4; j++) acc[r][j] = 0.f;
    for (int i = 0; i < 450; i++) {
        const float* hp = Hb + (size_t)i * NT;
        float hv[4];
#pragma unroll
        for (int j = 0; j < 4; j++) {
            int t = tid + 256 * j;
            hv[j] = (t < NT) ? hp[t] : 0.f;
        }
#pragma unroll
        for (int r = 0; r < 4; r++) {
            float w = ws[r * 450 + i];
#pragma unroll
            for (int j = 0; j < 4; j++) acc[r][j] += w * hv[j];
        }
    }
#pragma unroll
    for (int r = 0; r < 4; r++) {
        float s = 0.f;
#pragma unroll
        for (int j = 0; j < 4; j++) { int t = tid + 256 * j; if (t < NT) s += acc[r][j]; }
        s = blk_reduce<8>(s, red);
        float mean = s * (1.0f / NT);
        float* op = d_SC + ((size_t)(b * NS + s0 + r)) * NT;
#pragma unroll
        for (int j = 0; j < 4; j++) {
            int t = tid + 256 * j;
            if (t < NT) op[t] = acc[r][j] - mean;
        }
    }
}

// ---------- K4: partial covariance, 8 time-chunks, 7x7 register tile ----------
__global__ void k_covp() {
    int b = blockIdx.x, ch = blockIdx.y;   // ch < 8
    __shared__ float sh[NS * 28];
    int tid = threadIdx.x, tx = tid & 15, ty = tid >> 4;
    float acc[7][7];
#pragma unroll
    for (int a = 0; a < 7; a++)
#pragma unroll
        for (int c = 0; c < 7; c++) acc[a][c] = 0.f;
    int tbase0 = ch * 125;
    for (int cc = 0; cc < 5; cc++) {
        int tb = tbase0 + cc * 25;
        __syncthreads();
        for (int idx = tid; idx < NS * 25; idx += 256) {
            int i = idx / 25, tt = idx - i * 25;
            sh[i * 28 + tt] = d_SC[((size_t)(b * NS + i)) * NT + tb + tt];
        }
        __syncthreads();
        for (int tt = 0; tt < 25; tt++) {
            float ai[7], aj[7];
#pragma unroll
            for (int a = 0; a < 7; a++) { int i = ty + 16 * a; ai[a] = (i < NS) ? sh[i * 28 + tt] : 0.f; }
#pragma unroll
            for (int c = 0; c < 7; c++) { int j = tx + 16 * c; aj[c] = (j < NS) ? sh[j * 28 + tt] : 0.f; }
#pragma unroll
            for (int a = 0; a < 7; a++)
#pragma unroll
                for (int c = 0; c < 7; c++) acc[a][c] += ai[a] * aj[c];
        }
    }
#pragma unroll
    for (int a = 0; a < 7; a++)
#pragma unroll
        for (int c = 0; c < 7; c++) {
            int i = ty + 16 * a, j = tx + 16 * c;
            if (i < NS && j < NS)
                d_covp[((size_t)(b * 8 + ch) * NS + i) * NS + j] = acc[a][c];
        }
}

// ---------- K5: cov reduce + ridge + P = W cov W^T ----------
__global__ void k_affine(const float* __restrict__ waff) {
    int b = blockIdx.x;
    extern __shared__ float sm[];
    float* covs = sm;
    float* Ws = covs + NS * PIT;
    float* Ts = Ws + NS * PIT;
    int tid = threadIdx.x, tx = tid & 15, ty = tid >> 4;
    for (int idx = tid; idx < NS * NS; idx += 256) {
        int i = idx / NS, j = idx - i * NS;
        const float* pp = d_covp + (size_t)b * 8 * NS * NS + idx;
        float v = 0.f;
#pragma unroll
        for (int c = 0; c < 8; c++) v += pp[(size_t)c * NS * NS];
        v *= (1.0f / 999.0f);
        if (i == j) v += 1e-4f;
        covs[i * PIT + j] = v;
        Ws[i * PIT + j] = waff[idx];
    }
    __syncthreads();
    float acc[7][7];
#pragma unroll
    for (int a = 0; a < 7; a++)
#pragma unroll
        for (int c = 0; c < 7; c++) acc[a][c] = 0.f;
    for (int k = 0; k < NS; k++) {
        float wa[7], cb[7];
#pragma unroll
        for (int a = 0; a < 7; a++) { int i = ty + 16 * a; wa[a] = (i < NS) ? Ws[i * PIT + k] : 0.f; }
#pragma unroll
        for (int c = 0; c < 7; c++) { int j = tx + 16 * c; cb[c] = (j < NS) ? covs[k * PIT + j] : 0.f; }
#pragma unroll
        for (int a = 0; a < 7; a++)
#pragma unroll
            for (int c = 0; c < 7; c++) acc[a][c] += wa[a] * cb[c];
    }
#pragma unroll
    for (int a = 0; a < 7; a++)
#pragma unroll
        for (int c = 0; c < 7; c++) {
            int i = ty + 16 * a, j = tx + 16 * c;
            if (i < NS && j < NS) Ts[i * PIT + j] = acc[a][c];
        }
    __syncthreads();
#pragma unroll
    for (int a = 0; a < 7; a++)
#pragma unroll
        for (int c = 0; c < 7; c++) acc[a][c] = 0.f;
    for (int k = 0; k < NS; k++) {
        float ta[7], wb[7];
#pragma unroll
        for (int a = 0; a < 7; a++) { int i = ty + 16 * a; ta[a] = (i < NS) ? Ts[i * PIT + k] : 0.f; }
#pragma unroll
        for (int c = 0; c < 7; c++) { int j = tx + 16 * c; wb[c] = (j < NS) ? Ws[j * PIT + k] : 0.f; }
#pragma unroll
        for (int a = 0; a < 7; a++)
#pragma unroll
            for (int c = 0; c < 7; c++) acc[a][c] += ta[a] * wb[c];
    }
#pragma unroll
    for (int a = 0; a < 7; a++)
#pragma unroll
        for (int c = 0; c < 7; c++) {
            int i = ty + 16 * a, j = tx + 16 * c;
            if (i < NS && j < NS) d_P[(size_t)b * NS * NS + i * NS + j] = acc[a][c];
        }
}

// ---------- K6: Jacobi eigh (fused 2x2-block update) + logm + triu + FC ----------
__global__ void __launch_bounds__(1024, 1)
k_eig(const float* __restrict__ wfc, const float* __restrict__ bfc,
      float* __restrict__ out) {
    int b = blockIdx.x;
    extern __shared__ float sm[];
    float* As = sm;
    float* Vs = As + NS * PIT;
    __shared__ float cc[50], ssn[50];
    __shared__ int ppn[50], qqn[50];
    __shared__ float red[64];
    __shared__ float llog[NS];
    int tid = threadIdx.x;
    const float* Pb = d_P + (size_t)b * NS * NS;
    for (int idx = tid; idx < NS * NS; idx += 1024) {
        int i = idx / NS, j = idx - i * NS;
        As[i * PIT + j] = 0.5f * (Pb[i * NS + j] + Pb[j * NS + i]);
        Vs[i * PIT + j] = (i == j) ? 1.0f : 0.0f;
    }
    __syncthreads();

    for (int sweep = 0; sweep < 18; sweep++) {
        float o2 = 0.f, d2 = 0.f;
        for (int idx = tid; idx < NS * NS; idx += 1024) {
            int i = idx / NS, j = idx - i * NS;
            float v = As[i * PIT + j];
            if (i == j) d2 += v * v; else o2 += v * v;
        }
        float2 r = blk_reduce2<32>(o2, d2, red);
        if (r.x <= 1e-11f * r.y) break;

        for (int rnd = 0; rnd < 99; rnd++) {
            if (tid < 50) {
                int p, q;
                if (tid == 0) { p = rnd % 99; q = 99; }
                else { p = (rnd + tid) % 99; q = (rnd + 99 - tid) % 99; }
                float apq = As[p * PIT + q];
                float app = As[p * PIT + p], aqq = As[q * PIT + q];
                float c = 1.0f, s = 0.0f;
                if (fabsf(apq) > 1e-9f * sqrtf(fabsf(app * aqq)) + 1e-38f) {
                    float tau = (aqq - app) / (2.0f * apq);
                    float t = 1.0f / (fabsf(tau) + sqrtf(1.0f + tau * tau));
                    if (tau < 0.f) t = -t;
                    c = rsqrtf(1.0f + t * t);
                    s = t * c;
                }
                cc[tid] = c; ssn[tid] = s; ppn[tid] = p; qqn[tid] = q;
            }
            __syncthreads();
            // fused two-sided update: block (a,b) is self-contained
            for (int idx = tid; idx < 2500; idx += 1024) {
                int a = idx / 50, bb = idx - a * 50;
                float sa = ssn[a], sb = ssn[bb];
                if (sa != 0.0f || sb != 0.0f) {
                    float ca = cc[a], cb = cc[bb];
                    int pa = ppn[a], qa = qqn[a], pb = ppn[bb], qb = qqn[bb];
                    float x00 = As[pa * PIT + pb], x01 = As[pa * PIT + qb];
                    float x10 = As[qa * PIT + pb], x11 = As[qa * PIT + qb];
                    float y00 = cb * x00 - sb * x01, y01 = sb * x00 + cb * x01;
                    float y10 = cb * x10 - sb * x11, y11 = sb * x10 + cb * x11;
                    As[pa * PIT + pb] = ca * y00 - sa * y10;
                    As[qa * PIT + pb] = sa * y00 + ca * y10;
                    As[pa * PIT + qb] = ca * y01 - sa * y11;
                    As[qa * PIT + qb] = sa * y01 + ca * y11;
                }
            }
            // V accumulation (column rotations only) — independent of A update
            for (int idx = tid; idx < 5000; idx += 1024) {
                int k = idx / 100, i = idx - k * 100;
                float s = ssn[k];
                if (s != 0.0f) {
                    float c = cc[k]; int p = ppn[k], q = qqn[k];
                    float xp = Vs[i * PIT + p], xq = Vs[i * PIT + q];
                    Vs[i * PIT + p] = c * xp - s * xq;
                    Vs[i * PIT + q] = s * xp + c * xq;
                }
            }
            __syncthreads();
        }
    }

    // log eigenvalues, Vl = V * diag(log lam) into As
    if (tid < NS) llog[tid] = logf(fmaxf(As[tid * PIT + tid], 1e-6f));
    __syncthreads();
    for (int idx = tid; idx < NS * NS; idx += 1024) {
        int i = idx / NS, k = idx - i * NS;
        As[i * PIT + k] = Vs[i * PIT + k] * llog[k];
    }
    __syncthreads();

    float l0 = 0.f, l1 = 0.f, l2 = 0.f, l3 = 0.f;
    float* flat = out + 64 + (size_t)b * 5050;
    for (int idx = tid; idx < 5050; idx += 1024) {
        int i = (int)((201.0f - sqrtf(201.0f * 201.0f - 8.0f * (float)idx)) * 0.5f);
        if (i < 0) i = 0; if (i > 99) i = 99;
        while (i > 0 && i * (201 - i) / 2 > idx) i--;
        while (i < 99 && (i + 1) * (200 - i) / 2 <= idx) i++;
        int j = i + (idx - i * (201 - i) / 2);
        float a = 0.f;
        for (int k = 0; k < NS; k++) a += As[i * PIT + k] * Vs[j * PIT + k];
        float v = a * ((i == j) ? 1.0f : 1.41421356237309515f);
        flat[idx] = v;
        l0 += v * wfc[idx];
        l1 += v * wfc[5050 + idx];
        l2 += v * wfc[2 * 5050 + idx];
        l3 += v * wfc[3 * 5050 + idx];
    }
    l0 = blk_reduce<32>(l0, red);
    l1 = blk_reduce<32>(l1, red);
    l2 = blk_reduce<32>(l2, red);
    l3 = blk_reduce<32>(l3, red);
    if (tid == 0) {
        out[b * 4 + 0] = l0 + bfc[0];
        out[b * 4 + 1] = l1 + bfc[1];
        out[b * 4 + 2] = l2 + bfc[2];
        out[b * 4 + 3] = l3 + bfc[3];
    }
}

// ---------- launch ----------
extern "C" void kernel_launch(void* const* d_in, const int* in_sizes, int n_in,
                              void* d_out, int out_size) {
    const float* x = (const float*)d_in[0];
    PrepPs pps; BPs bps;
    for (int bi = 0; bi < 3; bi++) {
        int base = 1 + bi * 9;
        pps.p[bi].w1 = (const float*)d_in[base + 0];
        pps.p[bi].w2 = (const float*)d_in[base + 1];
        pps.p[bi].w3 = (const float*)d_in[base + 2];
        pps.p[bi].w4 = (const float*)d_in[base + 3];
        bps.p[bi].g1 = (const float*)d_in[base + 4];
        bps.p[bi].b1 = (const float*)d_in[base + 5];
        bps.p[bi].w5 = (const float*)d_in[base + 6];
        bps.p[bi].g2 = (const float*)d_in[base + 7];
        bps.p[bi].b2 = (const float*)d_in[base + 8];
    }
    const float* wsc  = (const float*)d_in[28];
    const float* waff = (const float*)d_in[29];
    const float* wfc  = (const float*)d_in[30];
    const float* bfc  = (const float*)d_in[31];

    const int SMEM_BLOCK = (NCH * NT + 1008 + ROWS_PER * NCH + ROWS_PER * 75 + 4 * NT) * 4;
    const int SMEM_AFF = 3 * NS * PIT * 4;
    const int SMEM_EIG = 2 * NS * PIT * 4;
    cudaFuncSetAttribute(k_block, cudaFuncAttributeMaxDynamicSharedMemorySize, SMEM_BLOCK);
    cudaFuncSetAttribute(k_affine, cudaFuncAttributeMaxDynamicSharedMemorySize, SMEM_AFF);
    cudaFuncSetAttribute(k_eig, cudaFuncAttributeMaxDynamicSharedMemorySize, SMEM_EIG);

    k_prep<<<3, 256>>>(pps);
    k_block<<<dim3(NB, 3, 5), 256, SMEM_BLOCK>>>(x, bps);
    k_sconv<<<dim3(NB, 25), 256>>>(wsc);
    k_covp<<<dim3(NB, 8), 256>>>();
    k_affine<<<NB, 256, SMEM_AFF>>>(waff);
    k_eig<<<NB, 1024, SMEM_EIG>>>(wfc, bfc, (float*)d_out);
}

// round 9
// speedup vs baseline: 2.4315x; 1.2072x over previous
#include <cuda_runtime.h>
#include <math.h>

#define NB   16
#define NCH  22
#define NT   1000
#define NEXP 300
#define NF   150
#define NS   100
#define PIT  101
#define ROWS_PER 30
#define SROWS 10

__device__ float d_Meff[3 * NF * NCH];
__device__ float d_H[(size_t)NB * 450 * NT];
__device__ float d_SC[(size_t)NB * NS * NT];
__device__ float d_covp[(size_t)NB * 8 * NS * NS];
__device__ float d_P[(size_t)NB * NS * NS];

struct BP  { const float *w5, *g1, *b1, *g2, *b2; };
struct BPs { BP p[3]; };
struct PrepP  { const float *w1, *w2, *w3, *w4; };
struct PrepPs { PrepP p[3]; };

// ---------- reductions ----------
template<int NW>
__device__ __forceinline__ float blk_reduce(float v, float* red) {
    int lane = threadIdx.x & 31, wid = threadIdx.x >> 5;
#pragma unroll
    for (int o = 16; o; o >>= 1) v += __shfl_xor_sync(0xffffffffu, v, o);
    if (lane == 0) red[wid] = v;
    __syncthreads();
    if (wid == 0) {
        float x = (lane < NW) ? red[lane] : 0.0f;
#pragma unroll
        for (int o = NW > 16 ? 16 : NW / 2; o; o >>= 1) x += __shfl_xor_sync(0xffffffffu, x, o);
        if (lane == 0) red[0] = x;
    }
    __syncthreads();
    float r = red[0];
    __syncthreads();
    return r;
}

template<int NW>
__device__ __forceinline__ float2 blk_reduce2(float a, float b, float* red) {
    int lane = threadIdx.x & 31, wid = threadIdx.x >> 5;
#pragma unroll
    for (int o = 16; o; o >>= 1) {
        a += __shfl_xor_sync(0xffffffffu, a, o);
        b += __shfl_xor_sync(0xffffffffu, b, o);
    }
    if (lane == 0) { red[wid] = a; red[32 + wid] = b; }
    __syncthreads();
    if (wid == 0) {
        float x = (lane < NW) ? red[lane] : 0.0f;
        float y = (lane < NW) ? red[32 + lane] : 0.0f;
#pragma unroll
        for (int o = NW > 16 ? 16 : NW / 2; o; o >>= 1) {
            x += __shfl_xor_sync(0xffffffffu, x, o);
            y += __shfl_xor_sync(0xffffffffu, y, o);
        }
        if (lane == 0) { red[0] = x; red[32] = y; }
    }
    __syncthreads();
    float2 r = make_float2(red[0], red[32]);
    __syncthreads();
    return r;
}

// ---------- K1: fold block weights into Meff (150x22) ----------
__global__ void k_prep(PrepPs ps) {
    int blk = blockIdx.x;
    PrepP w = ps.p[blk];
    __shared__ float w3s[NEXP * NCH];
    int tid = threadIdx.x;
    for (int g = tid; g < NEXP; g += 256) {
        float s = 0.f;
        for (int c = 0; c < NCH; c++) { float v = w.w3[g * NCH + c]; s += v * v; }
        float n = sqrtf(s);
        float sc = fminf(1.0f, 1.0f / (n + 1e-12f)) * w.w2[g];
        for (int c = 0; c < NCH; c++) w3s[g * NCH + c] = w.w3[g * NCH + c] * sc;
    }
    __syncthreads();
    float w10 = w.w1[0], w11 = w.w1[1], w12 = w.w1[2];
    for (int o = tid; o < NF; o += 256) {
        float m[NCH];
#pragma unroll
        for (int c = 0; c < NCH; c++) m[c] = 0.f;
        for (int g = 0; g < NEXP; g++) {
            float w4v = w.w4[o * NEXP + g];
#pragma unroll
            for (int c = 0; c < NCH; c++) m[c] += w4v * w3s[g * NCH + c];
        }
        for (int c = 0; c < NCH; c++) {
            float am = (c > 0) ? m[c - 1] : 0.f;
            float ap = (c < NCH - 1) ? m[c + 1] : 0.f;
            d_Meff[(blk * NF + o) * NCH + c] = w10 * ap + w11 * m[c] + w12 * am;
        }
    }
}

// ---------- K2: per-block Meff@x -> LN -> depthwise temporal conv -> LN ----------
template<int K>
__device__ __forceinline__ void block_impl(const float* __restrict__ x, BP bp, int blk,
                                           int b, int rc, float* sm, float* red) {
    const int Kh = K / 2;
    float* xsh  = sm;                       // 22*1000
    float* rbuf = xsh + NCH * NT;           // 1008
    float* meff = rbuf + 1008;
    float* w5s  = meff + ROWS_PER * NCH;
    float* g1s  = w5s + ROWS_PER * 75;
    float* b1s  = g1s + NT;
    float* g2s  = b1s + NT;
    float* b2s  = g2s + NT;
    int tid = threadIdx.x;
    int o0 = rc * ROWS_PER;
    bool act = tid < 250;
    int t0 = tid * 4;

    for (int i = tid; i < NCH * NT; i += 256) xsh[i] = x[(size_t)b * NCH * NT + i];
    for (int i = tid; i < ROWS_PER * NCH; i += 256) meff[i] = d_Meff[(blk * NF + o0) * NCH + i];
    for (int i = tid; i < ROWS_PER * K; i += 256) w5s[i] = bp.w5[o0 * K + i];
    for (int i = tid; i < NT; i += 256) {
        g1s[i] = bp.g1[i]; b1s[i] = bp.b1[i];
        g2s[i] = bp.g2[i]; b2s[i] = bp.b2[i];
    }
    __syncthreads();

    for (int oo = 0; oo < ROWS_PER; oo++) {
        float h0 = 0.f, h1 = 0.f, h2 = 0.f, h3 = 0.f;
        float s1 = 0.f, s2 = 0.f;
        if (act) {
            const float* mrow = meff + oo * NCH;
#pragma unroll
            for (int c = 0; c < NCH; c++) {
                float m = mrow[c];
                float4 xv = *reinterpret_cast<const float4*>(xsh + c * NT + t0);
                h0 += m * xv.x; h1 += m * xv.y; h2 += m * xv.z; h3 += m * xv.w;
            }
            s1 = h0 + h1 + h2 + h3;
            s2 = h0 * h0 + h1 * h1 + h2 * h2 + h3 * h3;
        }
        float2 r = blk_reduce2<8>(s1, s2, red);
        float mean = r.x * (1.0f / NT);
        float rstd = rsqrtf(r.y * (1.0f / NT) - mean * mean + 1e-5f);
        if (act) {
            float4 rv;
            rv.x = (h0 - mean) * rstd * g1s[t0 + 0] + b1s[t0 + 0];
            rv.y = (h1 - mean) * rstd * g1s[t0 + 1] + b1s[t0 + 1];
            rv.z = (h2 - mean) * rstd * g1s[t0 + 2] + b1s[t0 + 2];
            rv.w = (h3 - mean) * rstd * g1s[t0 + 3] + b1s[t0 + 3];
            *reinterpret_cast<float4*>(rbuf + t0) = rv;
        }
        __syncthreads();
        float c0 = 0.f, c1 = 0.f, c2 = 0.f, c3 = 0.f;
        s1 = 0.f; s2 = 0.f;
        if (act) {
            const float* wrow = w5s + oo * K;
            int i0 = t0 - Kh;
            float w0 = (i0 + 0 >= 0) ? rbuf[i0 + 0] : 0.f;
            float w1 = (i0 + 1 >= 0) ? rbuf[i0 + 1] : 0.f;
            float w2 = (i0 + 2 >= 0) ? rbuf[i0 + 2] : 0.f;
            float w3 = (i0 + 3 >= 0) ? rbuf[i0 + 3] : 0.f;
#pragma unroll
            for (int k = 0; k < K; k++) {
                float tap = wrow[k];
                c0 += tap * w0; c1 += tap * w1; c2 += tap * w2; c3 += tap * w3;
                w0 = w1; w1 = w2; w2 = w3;
                int tn = t0 + 4 + k - Kh;
                w3 = (tn >= 0 && tn < NT) ? rbuf[tn] : 0.f;
            }
            s1 = c0 + c1 + c2 + c3;
            s2 = c0 * c0 + c1 * c1 + c2 * c2 + c3 * c3;
        }
        float2 r2 = blk_reduce2<8>(s1, s2, red);
        float m2 = r2.x * (1.0f / NT);
        float rs2 = rsqrtf(r2.y * (1.0f / NT) - m2 * m2 + 1e-5f);
        float* outp = d_H + ((size_t)(b * 450 + blk * NF + o0 + oo)) * NT;
        if (act) {
            float4 ov;
            ov.x = (c0 - m2) * rs2 * g2s[t0 + 0] + b2s[t0 + 0];
            ov.y = (c1 - m2) * rs2 * g2s[t0 + 1] + b2s[t0 + 1];
            ov.z = (c2 - m2) * rs2 * g2s[t0 + 2] + b2s[t0 + 2];
            ov.w = (c3 - m2) * rs2 * g2s[t0 + 3] + b2s[t0 + 3];
            *reinterpret_cast<float4*>(outp + t0) = ov;
        }
    }
}

__global__ void k_block(const float* __restrict__ x, BPs bps) {
    int b = blockIdx.x, blk = blockIdx.y, rc = blockIdx.z;
    extern __shared__ float sm[];
    __shared__ float red[64];
    if (blk == 0)      block_impl<15>(x, bps.p[0], 0, b, rc, sm, red);
    else if (blk == 1) block_impl<75>(x, bps.p[1], 1, b, rc, sm, red);
    else               block_impl<55>(x, bps.p[2], 2, b, rc, sm, red);
}

// ---------- K3: spatial conv 450->100 + center over time (10 rows/CTA) ----------
__global__ void k_sconv(const float* __restrict__ wsc) {
    int b = blockIdx.x, s0 = blockIdx.y * SROWS;
    __shared__ float ws[SROWS * 450];
    __shared__ float red[64];
    int tid = threadIdx.x;
    for (int i = tid; i < SROWS * 450; i += 256) ws[i] = wsc[s0 * 450 + i];
    __syncthreads();
    const float* Hb = d_H + (size_t)b * 450 * NT;
    float acc[SROWS][4];
#pragma unroll
    for (int r = 0; r < SROWS; r++)
#pragma unroll
        for (int j = 0; j < 4; j++) acc[r][j] = 0.f;
    for (int i = 0; i < 450; i++) {
        const float* hp = Hb + (size_t)i * NT;
        float hv[4];
#pragma unroll
        for (int j = 0; j < 4; j++) {
            int t = tid + 256 * j;
            hv[j] = (t < NT) ? hp[t] : 0.f;
        }
#pragma unroll
        for (int r = 0; r < SROWS; r++) {
            float w = ws[r * 450 + i];
#pragma unroll
            for (int j = 0; j < 4; j++) acc[r][j] += w * hv[j];
        }
    }
#pragma unroll
    for (int r = 0; r < SROWS; r++) {
        float s = 0.f;
#pragma unroll
        for (int j = 0; j < 4; j++) { int t = tid + 256 * j; if (t < NT) s += acc[r][j]; }
        s = blk_reduce<8>(s, red);
        float mean = s * (1.0f / NT);
        float* op = d_SC + ((size_t)(b * NS + s0 + r)) * NT;
#pragma unroll
        for (int j = 0; j < 4; j++) {
            int t = tid + 256 * j;
            if (t < NT) op[t] = acc[r][j] - mean;
        }
    }
}

// ---------- K4: partial covariance, 8 time-chunks, 7x7 register tile ----------
__global__ void k_covp() {
    int b = blockIdx.x, ch = blockIdx.y;   // ch < 8
    __shared__ float sh[NS * 28];
    int tid = threadIdx.x, tx = tid & 15, ty = tid >> 4;
    float acc[7][7];
#pragma unroll
    for (int a = 0; a < 7; a++)
#pragma unroll
        for (int c = 0; c < 7; c++) acc[a][c] = 0.f;
    int tbase0 = ch * 125;
    for (int cc = 0; cc < 5; cc++) {
        int tb = tbase0 + cc * 25;
        __syncthreads();
        for (int idx = tid; idx < NS * 25; idx += 256) {
            int i = idx / 25, tt = idx - i * 25;
            sh[i * 28 + tt] = d_SC[((size_t)(b * NS + i)) * NT + tb + tt];
        }
        __syncthreads();
        for (int tt = 0; tt < 25; tt++) {
            float ai[7], aj[7];
#pragma unroll
            for (int a = 0; a < 7; a++) { int i = ty + 16 * a; ai[a] = (i < NS) ? sh[i * 28 + tt] : 0.f; }
#pragma unroll
            for (int c = 0; c < 7; c++) { int j = tx + 16 * c; aj[c] = (j < NS) ? sh[j * 28 + tt] : 0.f; }
#pragma unroll
            for (int a = 0; a < 7; a++)
#pragma unroll
                for (int c = 0; c < 7; c++) acc[a][c] += ai[a] * aj[c];
        }
    }
#pragma unroll
    for (int a = 0; a < 7; a++)
#pragma unroll
        for (int c = 0; c < 7; c++) {
            int i = ty + 16 * a, j = tx + 16 * c;
            if (i < NS && j < NS)
                d_covp[((size_t)(b * 8 + ch) * NS + i) * NS + j] = acc[a][c];
        }
}

// ---------- K5: cov reduce + ridge + P = W cov W^T ----------
__global__ void k_affine(const float* __restrict__ waff) {
    int b = blockIdx.x;
    extern __shared__ float sm[];
    float* covs = sm;
    float* Ws = covs + NS * PIT;
    float* Ts = Ws + NS * PIT;
    int tid = threadIdx.x, tx = tid & 15, ty = tid >> 4;
    for (int idx = tid; idx < NS * NS; idx += 256) {
        int i = idx / NS, j = idx - i * NS;
        const float* pp = d_covp + (size_t)b * 8 * NS * NS + idx;
        float v = 0.f;
#pragma unroll
        for (int c = 0; c < 8; c++) v += pp[(size_t)c * NS * NS];
        v *= (1.0f / 999.0f);
        if (i == j) v += 1e-4f;
        covs[i * PIT + j] = v;
        Ws[i * PIT + j] = waff[idx];
    }
    __syncthreads();
    float acc[7][7];
#pragma unroll
    for (int a = 0; a < 7; a++)
#pragma unroll
        for (int c = 0; c < 7; c++) acc[a][c] = 0.f;
    for (int k = 0; k < NS; k++) {
        float wa[7], cb[7];
#pragma unroll
        for (int a = 0; a < 7; a++) { int i = ty + 16 * a; wa[a] = (i < NS) ? Ws[i * PIT + k] : 0.f; }
#pragma unroll
        for (int c = 0; c < 7; c++) { int j = tx + 16 * c; cb[c] = (j < NS) ? covs[k * PIT + j] : 0.f; }
#pragma unroll
        for (int a = 0; a < 7; a++)
#pragma unroll
            for (int c = 0; c < 7; c++) acc[a][c] += wa[a] * cb[c];
    }
#pragma unroll
    for (int a = 0; a < 7; a++)
#pragma unroll
        for (int c = 0; c < 7; c++) {
            int i = ty + 16 * a, j = tx + 16 * c;
            if (i < NS && j < NS) Ts[i * PIT + j] = acc[a][c];
        }
    __syncthreads();
#pragma unroll
    for (int a = 0; a < 7; a++)
#pragma unroll
        for (int c = 0; c < 7; c++) acc[a][c] = 0.f;
    for (int k = 0; k < NS; k++) {
        float ta[7], wb[7];
#pragma unroll
        for (int a = 0; a < 7; a++) { int i = ty + 16 * a; ta[a] = (i < NS) ? Ts[i * PIT + k] : 0.f; }
#pragma unroll
        for (int c = 0; c < 7; c++) { int j = tx + 16 * c; wb[c] = (j < NS) ? Ws[j * PIT + k] : 0.f; }
#pragma unroll
        for (int a = 0; a < 7; a++)
#pragma unroll
            for (int c = 0; c < 7; c++) acc[a][c] += ta[a] * wb[c];
    }
#pragma unroll
    for (int a = 0; a < 7; a++)
#pragma unroll
        for (int c = 0; c < 7; c++) {
            int i = ty + 16 * a, j = tx + 16 * c;
            if (i < NS && j < NS) d_P[(size_t)b * NS * NS + i * NS + j] = acc[a][c];
        }
}

// ---------- K6: Jacobi eigh (half-symmetric fused update, overlapped params) ----------
__global__ void __launch_bounds__(1024, 1)
k_eig(const float* __restrict__ wfc, const float* __restrict__ bfc,
      float* __restrict__ out) {
    int b = blockIdx.x;
    extern __shared__ float sm[];
    float* As = sm;
    float* Vs = As + NS * PIT;
    __shared__ int pair_tab[99 * 50];
    __shared__ int tri_tab[1275];
    __shared__ float cc2[2][50], ss2[2][50];
    __shared__ float red[64];
    __shared__ float llog[NS];
    int tid = threadIdx.x;
    const float* Pb = d_P + (size_t)b * NS * NS;
    for (int idx = tid; idx < NS * NS; idx += 1024) {
        int i = idx / NS, j = idx - i * NS;
        As[i * PIT + j] = 0.5f * (Pb[i * NS + j] + Pb[j * NS + i]);
        Vs[i * PIT + j] = (i == j) ? 1.0f : 0.0f;
    }
    // tournament pair table: 99 rounds x 50 disjoint pairs
    for (int idx = tid; idx < 99 * 50; idx += 1024) {
        int rnd = idx / 50, k = idx - rnd * 50;
        int p, q;
        if (k == 0) { p = rnd; q = 99; }
        else { p = (rnd + k) % 99; q = (rnd + 99 - k) % 99; }
        pair_tab[idx] = p | (q << 16);
    }
    // triangular (a<=bb) block index table
    for (int idx = tid; idx < 2500; idx += 1024) {
        int a = idx / 50, bb = idx - a * 50;
        if (a <= bb) {
            int pos = a * 50 - (a * (a - 1)) / 2 + (bb - a);
            tri_tab[pos] = a | (bb << 16);
        }
    }
    __syncthreads();

    for (int sweep = 0; sweep < 15; sweep++) {
        float o2 = 0.f, d2 = 0.f;
        for (int idx = tid; idx < NS * NS; idx += 1024) {
            int i = idx / NS, j = idx - i * NS;
            float v = As[i * PIT + j];
            if (i == j) d2 += v * v; else o2 += v * v;
        }
        float2 r = blk_reduce2<32>(o2, d2, red);
        if (r.x <= 2e-10f * r.y) break;

        // params for round 0
        if (tid < 50) {
            int pq = pair_tab[tid];
            int p = pq & 0xffff, q = pq >> 16;
            float apq = As[p * PIT + q];
            float app = As[p * PIT + p], aqq = As[q * PIT + q];
            float c = 1.0f, s = 0.0f;
            if (fabsf(apq) > 1e-8f * sqrtf(fabsf(app * aqq)) + 1e-38f) {
                float tau = (aqq - app) / (2.0f * apq);
                float t = 1.0f / (fabsf(tau) + sqrtf(1.0f + tau * tau));
                if (tau < 0.f) t = -t;
                c = rsqrtf(1.0f + t * t);
                s = t * c;
            }
            cc2[0][tid] = c; ss2[0][tid] = s;
        }
        __syncthreads();

        for (int rnd = 0; rnd < 99; rnd++) {
            int buf = rnd & 1;
            const int* pt = pair_tab + rnd * 50;
            // A-update: half-symmetric fused 2x2-block rotations
            for (int idx = tid; idx < 1275; idx += 1024) {
                int ab = tri_tab[idx];
                int a = ab & 0xffff, bb = ab >> 16;
                float sa = ss2[buf][a], sb = ss2[buf][bb];
                if (sa == 0.f && sb == 0.f) continue;
                float ca = cc2[buf][a], cb = cc2[buf][bb];
                int pqa = pt[a]; int pa = pqa & 0xffff, qa = pqa >> 16;
                int pqb = pt[bb]; int pb = pqb & 0xffff, qb = pqb >> 16;
                float x00 = As[pa * PIT + pb], x01 = As[pa * PIT + qb];
                float x10 = As[qa * PIT + pb], x11 = As[qa * PIT + qb];
                float y00 = cb * x00 - sb * x01, y01 = sb * x00 + cb * x01;
                float y10 = cb * x10 - sb * x11, y11 = sb * x10 + cb * x11;
                float z00 = ca * y00 - sa * y10, z10 = sa * y00 + ca * y10;
                float z01 = ca * y01 - sa * y11, z11 = sa * y01 + ca * y11;
                As[pa * PIT + pb] = z00; As[pa * PIT + qb] = z01;
                As[qa * PIT + pb] = z10; As[qa * PIT + qb] = z11;
                if (a != bb) {
                    As[pb * PIT + pa] = z00; As[qb * PIT + pa] = z01;
                    As[pb * PIT + qa] = z10; As[qb * PIT + qa] = z11;
                }
            }
            __syncthreads();
            // V-update (all threads) + params for rnd+1 (threads 0-49, other buffer)
            for (int idx = tid; idx < 5000; idx += 1024) {
                int k = idx / 100, i = idx - k * 100;
                float s = ss2[buf][k];
                if (s != 0.f) {
                    float c = cc2[buf][k];
                    int pq = pt[k]; int p = pq & 0xffff, q = pq >> 16;
                    float xp = Vs[i * PIT + p], xq = Vs[i * PIT + q];
                    Vs[i * PIT + p] = c * xp - s * xq;
                    Vs[i * PIT + q] = s * xp + c * xq;
                }
            }
            if (tid < 50 && rnd < 98) {
                int pq = pair_tab[(rnd + 1) * 50 + tid];
                int p = pq & 0xffff, q = pq >> 16;
                float apq = As[p * PIT + q];
                float app = As[p * PIT + p], aqq = As[q * PIT + q];
                float c = 1.0f, s = 0.0f;
                if (fabsf(apq) > 1e-8f * sqrtf(fabsf(app * aqq)) + 1e-38f) {
                    float tau = (aqq - app) / (2.0f * apq);
                    float t = 1.0f / (fabsf(tau) + sqrtf(1.0f + tau * tau));
                    if (tau < 0.f) t = -t;
                    c = rsqrtf(1.0f + t * t);
                    s = t * c;
                }
                cc2[buf ^ 1][tid] = c; ss2[buf ^ 1][tid] = s;
            }
            __syncthreads();
        }
    }

    // log eigenvalues, Vl = V * diag(log lam) into As
    if (tid < NS) llog[tid] = logf(fmaxf(As[tid * PIT + tid], 1e-6f));
    __syncthreads();
    for (int idx = tid; idx < NS * NS; idx += 1024) {
        int i = idx / NS, k = idx - i * NS;
        As[i * PIT + k] = Vs[i * PIT + k] * llog[k];
    }
    __syncthreads();

    float l0 = 0.f, l1 = 0.f, l2 = 0.f, l3 = 0.f;
    float* flat = out + 64 + (size_t)b * 5050;
    for (int idx = tid; idx < 5050; idx += 1024) {
        int i = (int)((201.0f - sqrtf(201.0f * 201.0f - 8.0f * (float)idx)) * 0.5f);
        if (i < 0) i = 0; if (i > 99) i = 99;
        while (i > 0 && i * (201 - i) / 2 > idx) i--;
        while (i < 99 && (i + 1) * (200 - i) / 2 <= idx) i++;
        int j = i + (idx - i * (201 - i) / 2);
        float a = 0.f;
        for (int k = 0; k < NS; k++) a += As[i * PIT + k] * Vs[j * PIT + k];
        float v = a * ((i == j) ? 1.0f : 1.41421356237309515f);
        flat[idx] = v;
        l0 += v * wfc[idx];
        l1 += v * wfc[5050 + idx];
        l2 += v * wfc[2 * 5050 + idx];
        l3 += v * wfc[3 * 5050 + idx];
    }
    l0 = blk_reduce<32>(l0, red);
    l1 = blk_reduce<32>(l1, red);
    l2 = blk_reduce<32>(l2, red);
    l3 = blk_reduce<32>(l3, red);
    if (tid == 0) {
        out[b * 4 + 0] = l0 + bfc[0];
        out[b * 4 + 1] = l1 + bfc[1];
        out[b * 4 + 2] = l2 + bfc[2];
        out[b * 4 + 3] = l3 + bfc[3];
    }
}

// ---------- launch ----------
extern "C" void kernel_launch(void* const* d_in, const int* in_sizes, int n_in,
                              void* d_out, int out_size) {
    const float* x = (const float*)d_in[0];
    PrepPs pps; BPs bps;
    for (int bi = 0; bi < 3; bi++) {
        int base = 1 + bi * 9;
        pps.p[bi].w1 = (const float*)d_in[base + 0];
        pps.p[bi].w2 = (const float*)d_in[base + 1];
        pps.p[bi].w3 = (const float*)d_in[base + 2];
        pps.p[bi].w4 = (const float*)d_in[base + 3];
        bps.p[bi].g1 = (const float*)d_in[base + 4];
        bps.p[bi].b1 = (const float*)d_in[base + 5];
        bps.p[bi].w5 = (const float*)d_in[base + 6];
        bps.p[bi].g2 = (const float*)d_in[base + 7];
        bps.p[bi].b2 = (const float*)d_in[base + 8];
    }
    const float* wsc  = (const float*)d_in[28];
    const float* waff = (const float*)d_in[29];
    const float* wfc  = (const float*)d_in[30];
    const float* bfc  = (const float*)d_in[31];

    const int SMEM_BLOCK = (NCH * NT + 1008 + ROWS_PER * NCH + ROWS_PER * 75 + 4 * NT) * 4;
    const int SMEM_AFF = 3 * NS * PIT * 4;
    const int SMEM_EIG = 2 * NS * PIT * 4;
    cudaFuncSetAttribute(k_block, cudaFuncAttributeMaxDynamicSharedMemorySize, SMEM_BLOCK);
    cudaFuncSetAttribute(k_affine, cudaFuncAttributeMaxDynamicSharedMemorySize, SMEM_AFF);
    cudaFuncSetAttribute(k_eig, cudaFuncAttributeMaxDynamicSharedMemorySize, SMEM_EIG);

    k_prep<<<3, 256>>>(pps);
    k_block<<<dim3(NB, 3, 5), 256, SMEM_BLOCK>>>(x, bps);
    k_sconv<<<dim3(NB, 10), 256>>>(wsc);
    k_covp<<<dim3(NB, 8), 256>>>();
    k_affine<<<NB, 256, SMEM_AFF>>>(waff);
    k_eig<<<NB, 1024, SMEM_EIG>>>(wfc, bfc, (float*)d_out);
}

// round 11
// speedup vs baseline: 2.5844x; 1.0629x over previous
#include <cuda_runtime.h>
#include <math.h>

#define NB   16
#define NCH  22
#define NT   1000
#define NEXP 300
#define NF   150
#define NS   100
#define PIT  101
#define ROWS_PER 30
#define SROWS 10
#define MAXSW 15
#define MAXRND (MAXSW * 99)

__device__ float d_Meff[3 * NF * NCH];
__device__ float d_H[(size_t)NB * 450 * NT];
__device__ float d_SC[(size_t)NB * NS * NT];
__device__ float d_covp[(size_t)NB * 8 * NS * NS];
__device__ float d_P[(size_t)NB * NS * NS];
__device__ float2 d_rot[NB][MAXRND][50];
__device__ int   d_nr[NB];
__device__ float d_V[NB][NS][NS];
__device__ float d_eval[NB][NS];

struct BP  { const float *w5, *g1, *b1, *g2, *b2; };
struct BPs { BP p[3]; };
struct PrepP  { const float *w1, *w2, *w3, *w4; };
struct PrepPs { PrepP p[3]; };

// ---------- reductions ----------
template<int NW>
__device__ __forceinline__ float blk_reduce(float v, float* red) {
    int lane = threadIdx.x & 31, wid = threadIdx.x >> 5;
#pragma unroll
    for (int o = 16; o; o >>= 1) v += __shfl_xor_sync(0xffffffffu, v, o);
    if (lane == 0) red[wid] = v;
    __syncthreads();
    if (wid == 0) {
        float x = (lane < NW) ? red[lane] : 0.0f;
#pragma unroll
        for (int o = NW > 16 ? 16 : NW / 2; o; o >>= 1) x += __shfl_xor_sync(0xffffffffu, x, o);
        if (lane == 0) red[0] = x;
    }
    __syncthreads();
    float r = red[0];
    __syncthreads();
    return r;
}

template<int NW>
__device__ __forceinline__ float2 blk_reduce2(float a, float b, float* red) {
    int lane = threadIdx.x & 31, wid = threadIdx.x >> 5;
#pragma unroll
    for (int o = 16; o; o >>= 1) {
        a += __shfl_xor_sync(0xffffffffu, a, o);
        b += __shfl_xor_sync(0xffffffffu, b, o);
    }
    if (lane == 0) { red[wid] = a; red[32 + wid] = b; }
    __syncthreads();
    if (wid == 0) {
        float x = (lane < NW) ? red[lane] : 0.0f;
        float y = (lane < NW) ? red[32 + lane] : 0.0f;
#pragma unroll
        for (int o = NW > 16 ? 16 : NW / 2; o; o >>= 1) {
            x += __shfl_xor_sync(0xffffffffu, x, o);
            y += __shfl_xor_sync(0xffffffffu, y, o);
        }
        if (lane == 0) { red[0] = x; red[32] = y; }
    }
    __syncthreads();
    float2 r = make_float2(red[0], red[32]);
    __syncthreads();
    return r;
}

// ---------- K1: fold block weights into Meff (150x22) ----------
__global__ void k_prep(PrepPs ps) {
    int blk = blockIdx.x;
    PrepP w = ps.p[blk];
    __shared__ float w3s[NEXP * NCH];
    int tid = threadIdx.x;
    for (int g = tid; g < NEXP; g += 256) {
        float s = 0.f;
        for (int c = 0; c < NCH; c++) { float v = w.w3[g * NCH + c]; s += v * v; }
        float n = sqrtf(s);
        float sc = fminf(1.0f, 1.0f / (n + 1e-12f)) * w.w2[g];
        for (int c = 0; c < NCH; c++) w3s[g * NCH + c] = w.w3[g * NCH + c] * sc;
    }
    __syncthreads();
    float w10 = w.w1[0], w11 = w.w1[1], w12 = w.w1[2];
    for (int o = tid; o < NF; o += 256) {
        float m[NCH];
#pragma unroll
        for (int c = 0; c < NCH; c++) m[c] = 0.f;
        for (int g = 0; g < NEXP; g++) {
            float w4v = w.w4[o * NEXP + g];
#pragma unroll
            for (int c = 0; c < NCH; c++) m[c] += w4v * w3s[g * NCH + c];
        }
        for (int c = 0; c < NCH; c++) {
            float am = (c > 0) ? m[c - 1] : 0.f;
            float ap = (c < NCH - 1) ? m[c + 1] : 0.f;
            d_Meff[(blk * NF + o) * NCH + c] = w10 * ap + w11 * m[c] + w12 * am;
        }
    }
}

// ---------- K2: per-block Meff@x -> LN -> depthwise temporal conv -> LN ----------
template<int K>
__device__ __forceinline__ void block_impl(const float* __restrict__ x, BP bp, int blk,
                                           int b, int rc, float* sm, float* red) {
    const int Kh = K / 2;
    float* xsh  = sm;
    float* rbuf = xsh + NCH * NT;
    float* meff = rbuf + 1008;
    float* w5s  = meff + ROWS_PER * NCH;
    float* g1s  = w5s + ROWS_PER * 75;
    float* b1s  = g1s + NT;
    float* g2s  = b1s + NT;
    float* b2s  = g2s + NT;
    int tid = threadIdx.x;
    int o0 = rc * ROWS_PER;
    bool act = tid < 250;
    int t0 = tid * 4;

    for (int i = tid; i < NCH * NT; i += 256) xsh[i] = x[(size_t)b * NCH * NT + i];
    for (int i = tid; i < ROWS_PER * NCH; i += 256) meff[i] = d_Meff[(blk * NF + o0) * NCH + i];
    for (int i = tid; i < ROWS_PER * K; i += 256) w5s[i] = bp.w5[o0 * K + i];
    for (int i = tid; i < NT; i += 256) {
        g1s[i] = bp.g1[i]; b1s[i] = bp.b1[i];
        g2s[i] = bp.g2[i]; b2s[i] = bp.b2[i];
    }
    __syncthreads();

    for (int oo = 0; oo < ROWS_PER; oo++) {
        float h0 = 0.f, h1 = 0.f, h2 = 0.f, h3 = 0.f;
        float s1 = 0.f, s2 = 0.f;
        if (act) {
            const float* mrow = meff + oo * NCH;
#pragma unroll
            for (int c = 0; c < NCH; c++) {
                float m = mrow[c];
                float4 xv = *reinterpret_cast<const float4*>(xsh + c * NT + t0);
                h0 += m * xv.x; h1 += m * xv.y; h2 += m * xv.z; h3 += m * xv.w;
            }
            s1 = h0 + h1 + h2 + h3;
            s2 = h0 * h0 + h1 * h1 + h2 * h2 + h3 * h3;
        }
        float2 r = blk_reduce2<8>(s1, s2, red);
        float mean = r.x * (1.0f / NT);
        float rstd = rsqrtf(r.y * (1.0f / NT) - mean * mean + 1e-5f);
        if (act) {
            float4 rv;
            rv.x = (h0 - mean) * rstd * g1s[t0 + 0] + b1s[t0 + 0];
            rv.y = (h1 - mean) * rstd * g1s[t0 + 1] + b1s[t0 + 1];
            rv.z = (h2 - mean) * rstd * g1s[t0 + 2] + b1s[t0 + 2];
            rv.w = (h3 - mean) * rstd * g1s[t0 + 3] + b1s[t0 + 3];
            *reinterpret_cast<float4*>(rbuf + t0) = rv;
        }
        __syncthreads();
        float c0 = 0.f, c1 = 0.f, c2 = 0.f, c3 = 0.f;
        s1 = 0.f; s2 = 0.f;
        if (act) {
            const float* wrow = w5s + oo * K;
            int i0 = t0 - Kh;
            float w0 = (i0 + 0 >= 0) ? rbuf[i0 + 0] : 0.f;
            float w1 = (i0 + 1 >= 0) ? rbuf[i0 + 1] : 0.f;
            float w2 = (i0 + 2 >= 0) ? rbuf[i0 + 2] : 0.f;
            float w3 = (i0 + 3 >= 0) ? rbuf[i0 + 3] : 0.f;
#pragma unroll
            for (int k = 0; k < K; k++) {
                float tap = wrow[k];
                c0 += tap * w0; c1 += tap * w1; c2 += tap * w2; c3 += tap * w3;
                w0 = w1; w1 = w2; w2 = w3;
                int tn = t0 + 4 + k - Kh;
                w3 = (tn >= 0 && tn < NT) ? rbuf[tn] : 0.f;
            }
            s1 = c0 + c1 + c2 + c3;
            s2 = c0 * c0 + c1 * c1 + c2 * c2 + c3 * c3;
        }
        float2 r2 = blk_reduce2<8>(s1, s2, red);
        float m2 = r2.x * (1.0f / NT);
        float rs2 = rsqrtf(r2.y * (1.0f / NT) - m2 * m2 + 1e-5f);
        float* outp = d_H + ((size_t)(b * 450 + blk * NF + o0 + oo)) * NT;
        if (act) {
            float4 ov;
            ov.x = (c0 - m2) * rs2 * g2s[t0 + 0] + b2s[t0 + 0];
            ov.y = (c1 - m2) * rs2 * g2s[t0 + 1] + b2s[t0 + 1];
            ov.z = (c2 - m2) * rs2 * g2s[t0 + 2] + b2s[t0 + 2];
            ov.w = (c3 - m2) * rs2 * g2s[t0 + 3] + b2s[t0 + 3];
            *reinterpret_cast<float4*>(outp + t0) = ov;
        }
    }
}

__global__ void k_block(const float* __restrict__ x, BPs bps) {
    int b = blockIdx.x, blk = blockIdx.y, rc = blockIdx.z;
    extern __shared__ float sm[];
    __shared__ float red[64];
    if (blk == 0)      block_impl<15>(x, bps.p[0], 0, b, rc, sm, red);
    else if (blk == 1) block_impl<75>(x, bps.p[1], 1, b, rc, sm, red);
    else               block_impl<55>(x, bps.p[2], 2, b, rc, sm, red);
}

// ---------- K3: spatial conv 450->100 + center over time ----------
__global__ void k_sconv(const float* __restrict__ wsc) {
    int b = blockIdx.x, s0 = blockIdx.y * SROWS;
    __shared__ float ws[SROWS * 450];
    __shared__ float red[64];
    int tid = threadIdx.x;
    for (int i = tid; i < SROWS * 450; i += 256) ws[i] = wsc[s0 * 450 + i];
    __syncthreads();
    const float* Hb = d_H + (size_t)b * 450 * NT;
    float acc[SROWS][4];
#pragma unroll
    for (int r = 0; r < SROWS; r++)
#pragma unroll
        for (int j = 0; j < 4; j++) acc[r][j] = 0.f;
    for (int i = 0; i < 450; i++) {
        const float* hp = Hb + (size_t)i * NT;
        float hv[4];
#pragma unroll
        for (int j = 0; j < 4; j++) {
            int t = tid + 256 * j;
            hv[j] = (t < NT) ? hp[t] : 0.f;
        }
#pragma unroll
        for (int r = 0; r < SROWS; r++) {
            float w = ws[r * 450 + i];
#pragma unroll
            for (int j = 0; j < 4; j++) acc[r][j] += w * hv[j];
        }
    }
#pragma unroll
    for (int r = 0; r < SROWS; r++) {
        float s = 0.f;
#pragma unroll
        for (int j = 0; j < 4; j++) { int t = tid + 256 * j; if (t < NT) s += acc[r][j]; }
        s = blk_reduce<8>(s, red);
        float mean = s * (1.0f / NT);
        float* op = d_SC + ((size_t)(b * NS + s0 + r)) * NT;
#pragma unroll
        for (int j = 0; j < 4; j++) {
            int t = tid + 256 * j;
            if (t < NT) op[t] = acc[r][j] - mean;
        }
    }
}

// ---------- K4: partial covariance ----------
__global__ void k_covp() {
    int b = blockIdx.x, ch = blockIdx.y;
    __shared__ float sh[NS * 28];
    int tid = threadIdx.x, tx = tid & 15, ty = tid >> 4;
    float acc[7][7];
#pragma unroll
    for (int a = 0; a < 7; a++)
#pragma unroll
        for (int c = 0; c < 7; c++) acc[a][c] = 0.f;
    int tbase0 = ch * 125;
    for (int cc = 0; cc < 5; cc++) {
        int tb = tbase0 + cc * 25;
        __syncthreads();
        for (int idx = tid; idx < NS * 25; idx += 256) {
            int i = idx / 25, tt = idx - i * 25;
            sh[i * 28 + tt] = d_SC[((size_t)(b * NS + i)) * NT + tb + tt];
        }
        __syncthreads();
        for (int tt = 0; tt < 25; tt++) {
            float ai[7], aj[7];
#pragma unroll
            for (int a = 0; a < 7; a++) { int i = ty + 16 * a; ai[a] = (i < NS) ? sh[i * 28 + tt] : 0.f; }
#pragma unroll
            for (int c = 0; c < 7; c++) { int j = tx + 16 * c; aj[c] = (j < NS) ? sh[j * 28 + tt] : 0.f; }
#pragma unroll
            for (int a = 0; a < 7; a++)
#pragma unroll
                for (int c = 0; c < 7; c++) acc[a][c] += ai[a] * aj[c];
        }
    }
#pragma unroll
    for (int a = 0; a < 7; a++)
#pragma unroll
        for (int c = 0; c < 7; c++) {
            int i = ty + 16 * a, j = tx + 16 * c;
            if (i < NS && j < NS)
                d_covp[((size_t)(b * 8 + ch) * NS + i) * NS + j] = acc[a][c];
        }
}

// ---------- K5: cov reduce + ridge + P = W cov W^T ----------
__global__ void k_affine(const float* __restrict__ waff) {
    int b = blockIdx.x;
    extern __shared__ float sm[];
    float* covs = sm;
    float* Ws = covs + NS * PIT;
    float* Ts = Ws + NS * PIT;
    int tid = threadIdx.x, tx = tid & 15, ty = tid >> 4;
    for (int idx = tid; idx < NS * NS; idx += 256) {
        int i = idx / NS, j = idx - i * NS;
        const float* pp = d_covp + (size_t)b * 8 * NS * NS + idx;
        float v = 0.f;
#pragma unroll
        for (int c = 0; c < 8; c++) v += pp[(size_t)c * NS * NS];
        v *= (1.0f / 999.0f);
        if (i == j) v += 1e-4f;
        covs[i * PIT + j] = v;
        Ws[i * PIT + j] = waff[idx];
    }
    __syncthreads();
    float acc[7][7];
#pragma unroll
    for (int a = 0; a < 7; a++)
#pragma unroll
        for (int c = 0; c < 7; c++) acc[a][c] = 0.f;
    for (int k = 0; k < NS; k++) {
        float wa[7], cb[7];
#pragma unroll
        for (int a = 0; a < 7; a++) { int i = ty + 16 * a; wa[a] = (i < NS) ? Ws[i * PIT + k] : 0.f; }
#pragma unroll
        for (int c = 0; c < 7; c++) { int j = tx + 16 * c; cb[c] = (j < NS) ? covs[k * PIT + j] : 0.f; }
#pragma unroll
        for (int a = 0; a < 7; a++)
#pragma unroll
            for (int c = 0; c < 7; c++) acc[a][c] += wa[a] * cb[c];
    }
#pragma unroll
    for (int a = 0; a < 7; a++)
#pragma unroll
        for (int c = 0; c < 7; c++) {
            int i = ty + 16 * a, j = tx + 16 * c;
            if (i < NS && j < NS) Ts[i * PIT + j] = acc[a][c];
        }
    __syncthreads();
#pragma unroll
    for (int a = 0; a < 7; a++)
#pragma unroll
        for (int c = 0; c < 7; c++) acc[a][c] = 0.f;
    for (int k = 0; k < NS; k++) {
        float ta[7], wb[7];
#pragma unroll
        for (int a = 0; a < 7; a++) { int i = ty + 16 * a; ta[a] = (i < NS) ? Ts[i * PIT + k] : 0.f; }
#pragma unroll
        for (int c = 0; c < 7; c++) { int j = tx + 16 * c; wb[c] = (j < NS) ? Ws[j * PIT + k] : 0.f; }
#pragma unroll
        for (int a = 0; a < 7; a++)
#pragma unroll
            for (int c = 0; c < 7; c++) acc[a][c] += ta[a] * wb[c];
    }
#pragma unroll
    for (int a = 0; a < 7; a++)
#pragma unroll
        for (int c = 0; c < 7; c++) {
            int i = ty + 16 * a, j = tx + 16 * c;
            if (i < NS && j < NS) d_P[(size_t)b * NS * NS + i * NS + j] = acc[a][c];
        }
}

// ---------- K6a: Jacobi on A only; rotations logged to gmem ----------
__global__ void __launch_bounds__(512, 1)
k_eigA() {
    int b = blockIdx.x;
    extern __shared__ float sm[];
    float* As = sm;
    __shared__ int pair_tab[99 * 50];
    __shared__ int tri_tab[1275];
    __shared__ float cc[50], ss[50];
    __shared__ float red[64];
    int tid = threadIdx.x;
    const float* Pb = d_P + (size_t)b * NS * NS;
    for (int idx = tid; idx < NS * NS; idx += 512) {
        int i = idx / NS, j = idx - i * NS;
        As[i * PIT + j] = 0.5f * (Pb[i * NS + j] + Pb[j * NS + i]);
    }
    for (int idx = tid; idx < 99 * 50; idx += 512) {
        int rnd = idx / 50, k = idx - rnd * 50;
        int p, q;
        if (k == 0) { p = rnd; q = 99; }
        else { p = (rnd + k) % 99; q = (rnd + 99 - k) % 99; }
        pair_tab[idx] = p | (q << 16);
    }
    for (int idx = tid; idx < 2500; idx += 512) {
        int a = idx / 50, bb = idx - a * 50;
        if (a <= bb) {
            int pos = a * 50 - (a * (a - 1)) / 2 + (bb - a);
            tri_tab[pos] = a | (bb << 16);
        }
    }
    __syncthreads();

    int nr = 0;
    for (int sweep = 0; sweep < MAXSW; sweep++) {
        float o2 = 0.f, d2 = 0.f;
        for (int idx = tid; idx < NS * NS; idx += 512) {
            int i = idx / NS, j = idx - i * NS;
            float v = As[i * PIT + j];
            if (i == j) d2 += v * v; else o2 += v * v;
        }
        float2 r = blk_reduce2<16>(o2, d2, red);
        if (r.x <= 2e-10f * r.y) break;

        for (int rnd = 0; rnd < 99; rnd++) {
            const int* pt = pair_tab + rnd * 50;
            if (tid < 50) {
                int pq = pt[tid];
                int p = pq & 0xffff, q = pq >> 16;
                float apq = As[p * PIT + q];
                float app = As[p * PIT + p], aqq = As[q * PIT + q];
                float c = 1.0f, s = 0.0f;
                if (fabsf(apq) > 1e-8f * sqrtf(fabsf(app * aqq)) + 1e-38f) {
                    float tau = (aqq - app) / (2.0f * apq);
                    float t = 1.0f / (fabsf(tau) + sqrtf(1.0f + tau * tau));
                    if (tau < 0.f) t = -t;
                    c = rsqrtf(1.0f + t * t);
                    s = t * c;
                }
                cc[tid] = c; ss[tid] = s;
                d_rot[b][nr][tid] = make_float2(c, s);
            }
            __syncthreads();
            for (int idx = tid; idx < 1275; idx += 512) {
                int ab = tri_tab[idx];
                int a = ab & 0xffff, bb = ab >> 16;
                float sa = ss[a], sb = ss[bb];
                if (sa == 0.f && sb == 0.f) continue;
                float ca = cc[a], cb = cc[bb];
                int pqa = pt[a]; int pa = pqa & 0xffff, qa = pqa >> 16;
                int pqb = pt[bb]; int pb = pqb & 0xffff, qb = pqb >> 16;
                float x00 = As[pa * PIT + pb], x01 = As[pa * PIT + qb];
                float x10 = As[qa * PIT + pb], x11 = As[qa * PIT + qb];
                float y00 = cb * x00 - sb * x01, y01 = sb * x00 + cb * x01;
                float y10 = cb * x10 - sb * x11, y11 = sb * x10 + cb * x11;
                float z00 = ca * y00 - sa * y10, z10 = sa * y00 + ca * y10;
                float z01 = ca * y01 - sa * y11, z11 = sa * y01 + ca * y11;
                As[pa * PIT + pb] = z00; As[pa * PIT + qb] = z01;
                As[qa * PIT + pb] = z10; As[qa * PIT + qb] = z11;
                if (a != bb) {
                    As[pb * PIT + pa] = z00; As[qb * PIT + pa] = z01;
                    As[pb * PIT + qa] = z10; As[qb * PIT + qa] = z11;
                }
            }
            __syncthreads();
            nr++;
        }
    }
    if (tid == 0) d_nr[b] = nr;
    if (tid < NS) d_eval[b][tid] = As[tid * PIT + tid];
}

// ---------- K6b: replay rotation log onto V (rows split across CTAs) ----------
__global__ void __launch_bounds__(256, 1)
k_vrep() {
    int b = blockIdx.x, ch = blockIdx.y;
    int r0 = ch * 25;
    __shared__ float Vr[25 * PIT];
    __shared__ float2 pbuf[2][50];
    int tid = threadIdx.x;
    for (int idx = tid; idx < 25 * NS; idx += 256) {
        int i = idx / NS, j = idx - i * NS;
        Vr[i * PIT + j] = (r0 + i == j) ? 1.0f : 0.0f;
    }
    int nr = d_nr[b];
    if (tid < 50 && nr > 0) pbuf[0][tid] = d_rot[b][0][tid];
    __syncthreads();

    for (int rnd = 0; rnd < nr; rnd++) {
        int buf = rnd & 1;
        float2 nxt = make_float2(1.f, 0.f);
        bool pf = (tid < 50) && (rnd + 1 < nr);
        if (pf) nxt = d_rot[b][rnd + 1][tid];
        int rt = rnd % 99;
        for (int idx = tid; idx < 25 * 50; idx += 256) {
            int i = idx / 50, k = idx - i * 50;
            float2 cs = pbuf[buf][k];
            if (cs.y != 0.f) {
                int p, q;
                if (k == 0) { p = rt; q = 99; }
                else {
                    p = rt + k;       if (p >= 99) p -= 99;
                    q = rt + 99 - k;  if (q >= 99) q -= 99;
                }
                float xp = Vr[i * PIT + p], xq = Vr[i * PIT + q];
                Vr[i * PIT + p] = cs.x * xp - cs.y * xq;
                Vr[i * PIT + q] = cs.y * xp + cs.x * xq;
            }
        }
        if (pf) pbuf[buf ^ 1][tid] = nxt;
        __syncthreads();
    }
    for (int idx = tid; idx < 25 * NS; idx += 256) {
        int i = idx / NS, j = idx - i * NS;
        d_V[b][r0 + i][j] = Vr[i * PIT + j];
    }
}

// ---------- K6c: epilogue logm triu + FC ----------
__global__ void __launch_bounds__(1024, 1)
k_epi(const float* __restrict__ wfc, const float* __restrict__ bfc,
      float* __restrict__ out) {
    int b = blockIdx.x;
    extern __shared__ float sm[];
    float* As = sm;
    float* Vs = As + NS * PIT;
    __shared__ float red[64];
    __shared__ float llog[NS];
    int tid = threadIdx.x;
    if (tid < NS) llog[tid] = logf(fmaxf(d_eval[b][tid], 1e-6f));
    for (int idx = tid; idx < NS * NS; idx += 1024) {
        int i = idx / NS, k = idx - i * NS;
        Vs[i * PIT + k] = d_V[b][i][k];
    }
    __syncthreads();
    for (int idx = tid; idx < NS * NS; idx += 1024) {
        int i = idx / NS, k = idx - i * NS;
        As[i * PIT + k] = Vs[i * PIT + k] * llog[k];
    }
    __syncthreads();

    float l0 = 0.f, l1 = 0.f, l2 = 0.f, l3 = 0.f;
    float* flat = out + 64 + (size_t)b * 5050;
    for (int idx = tid; idx < 5050; idx += 1024) {
        int i = (int)((201.0f - sqrtf(201.0f * 201.0f - 8.0f * (float)idx)) * 0.5f);
        if (i < 0) i = 0; if (i > 99) i = 99;
        while (i > 0 && i * (201 - i) / 2 > idx) i--;
        while (i < 99 && (i + 1) * (200 - i) / 2 <= idx) i++;
        int j = i + (idx - i * (201 - i) / 2);
        float a = 0.f;
        for (int k = 0; k < NS; k++) a += As[i * PIT + k] * Vs[j * PIT + k];
        float v = a * ((i == j) ? 1.0f : 1.41421356237309515f);
        flat[idx] = v;
        l0 += v * wfc[idx];
        l1 += v * wfc[5050 + idx];
        l2 += v * wfc[2 * 5050 + idx];
        l3 += v * wfc[3 * 5050 + idx];
    }
    l0 = blk_reduce<32>(l0, red);
    l1 = blk_reduce<32>(l1, red);
    l2 = blk_reduce<32>(l2, red);
    l3 = blk_reduce<32>(l3, red);
    if (tid == 0) {
        out[b * 4 + 0] = l0 + bfc[0];
        out[b * 4 + 1] = l1 + bfc[1];
        out[b * 4 + 2] = l2 + bfc[2];
        out[b * 4 + 3] = l3 + bfc[3];
    }
}

// ---------- launch ----------
extern "C" void kernel_launch(void* const* d_in, const int* in_sizes, int n_in,
                              void* d_out, int out_size) {
    const float* x = (const float*)d_in[0];
    PrepPs pps; BPs bps;
    for (int bi = 0; bi < 3; bi++) {
        int base = 1 + bi * 9;
        pps.p[bi].w1 = (const float*)d_in[base + 0];
        pps.p[bi].w2 = (const float*)d_in[base + 1];
        pps.p[bi].w3 = (const float*)d_in[base + 2];
        pps.p[bi].w4 = (const float*)d_in[base + 3];
        bps.p[bi].g1 = (const float*)d_in[base + 4];
        bps.p[bi].b1 = (const float*)d_in[base + 5];
        bps.p[bi].w5 = (const float*)d_in[base + 6];
        bps.p[bi].g2 = (const float*)d_in[base + 7];
        bps.p[bi].b2 = (const float*)d_in[base + 8];
    }
    const float* wsc  = (const float*)d_in[28];
    const float* waff = (const float*)d_in[29];
    const float* wfc  = (const float*)d_in[30];
    const float* bfc  = (const float*)d_in[31];

    const int SMEM_BLOCK = (NCH * NT + 1008 + ROWS_PER * NCH + ROWS_PER * 75 + 4 * NT) * 4;
    const int SMEM_AFF = 3 * NS * PIT * 4;
    const int SMEM_A   = NS * PIT * 4;
    const int SMEM_EPI = 2 * NS * PIT * 4;
    cudaFuncSetAttribute(k_block, cudaFuncAttributeMaxDynamicSharedMemorySize, SMEM_BLOCK);
    cudaFuncSetAttribute(k_affine, cudaFuncAttributeMaxDynamicSharedMemorySize, SMEM_AFF);
    cudaFuncSetAttribute(k_eigA, cudaFuncAttributeMaxDynamicSharedMemorySize, SMEM_A);
    cudaFuncSetAttribute(k_epi, cudaFuncAttributeMaxDynamicSharedMemorySize, SMEM_EPI);

    k_prep<<<3, 256>>>(pps);
    k_block<<<dim3(NB, 3, 5), 256, SMEM_BLOCK>>>(x, bps);
    k_sconv<<<dim3(NB, 10), 256>>>(wsc);
    k_covp<<<dim3(NB, 8), 256>>>();
    k_affine<<<NB, 256, SMEM_AFF>>>(waff);
    k_eigA<<<NB, 512, SMEM_A>>>();
    k_vrep<<<dim3(NB, 4), 256>>>();
    k_epi<<<NB, 1024, SMEM_EPI>>>(wfc, bfc, (float*)d_out);
}

// round 14
// speedup vs baseline: 3.1046x; 1.2013x over previous
#include <cuda_runtime.h>
#include <math.h>

#define NB   16
#define NCH  22
#define NT   1000
#define NEXP 300
#define NF   150
#define NS   100
#define PIT  101
#define ROWS_PER 30
#define SROWS 10
#define MAXSW 15
#define MAXRND (MAXSW * 99)
#define VROWS 10

__device__ float d_Meff[3 * NF * NCH];
__device__ float d_H[(size_t)NB * 450 * NT];
__device__ float d_SC[(size_t)NB * NS * NT];
__device__ float d_covp[(size_t)NB * 8 * NS * NS];
__device__ float d_P[(size_t)NB * NS * NS];
__device__ float2 d_rot[NB][MAXRND][50];
__device__ int   d_nr[NB];
__device__ float d_V[NB][NS][NS];
__device__ float d_eval[NB][NS];

struct BP  { const float *w5, *g1, *b1, *g2, *b2; };
struct BPs { BP p[3]; };
struct PrepP  { const float *w1, *w2, *w3, *w4; };
struct PrepPs { PrepP p[3]; };

// ---------- reductions ----------
template<int NW>
__device__ __forceinline__ float blk_reduce(float v, float* red) {
    int lane = threadIdx.x & 31, wid = threadIdx.x >> 5;
#pragma unroll
    for (int o = 16; o; o >>= 1) v += __shfl_xor_sync(0xffffffffu, v, o);
    if (lane == 0) red[wid] = v;
    __syncthreads();
    if (wid == 0) {
        float x = (lane < NW) ? red[lane] : 0.0f;
#pragma unroll
        for (int o = NW > 16 ? 16 : NW / 2; o; o >>= 1) x += __shfl_xor_sync(0xffffffffu, x, o);
        if (lane == 0) red[0] = x;
    }
    __syncthreads();
    float r = red[0];
    __syncthreads();
    return r;
}

template<int NW>
__device__ __forceinline__ float2 blk_reduce2(float a, float b, float* red) {
    int lane = threadIdx.x & 31, wid = threadIdx.x >> 5;
#pragma unroll
    for (int o = 16; o; o >>= 1) {
        a += __shfl_xor_sync(0xffffffffu, a, o);
        b += __shfl_xor_sync(0xffffffffu, b, o);
    }
    if (lane == 0) { red[wid] = a; red[32 + wid] = b; }
    __syncthreads();
    if (wid == 0) {
        float x = (lane < NW) ? red[lane] : 0.0f;
        float y = (lane < NW) ? red[32 + lane] : 0.0f;
#pragma unroll
        for (int o = NW > 16 ? 16 : NW / 2; o; o >>= 1) {
            x += __shfl_xor_sync(0xffffffffu, x, o);
            y += __shfl_xor_sync(0xffffffffu, y, o);
        }
        if (lane == 0) { red[0] = x; red[32] = y; }
    }
    __syncthreads();
    float2 r = make_float2(red[0], red[32]);
    __syncthreads();
    return r;
}

// ---------- K1: fold block weights into Meff (150x22) ----------
__global__ void k_prep(PrepPs ps) {
    int blk = blockIdx.x;
    PrepP w = ps.p[blk];
    __shared__ float w3s[NEXP * NCH];
    int tid = threadIdx.x;
    for (int g = tid; g < NEXP; g += 256) {
        float s = 0.f;
        for (int c = 0; c < NCH; c++) { float v = w.w3[g * NCH + c]; s += v * v; }
        float n = sqrtf(s);
        float sc = fminf(1.0f, 1.0f / (n + 1e-12f)) * w.w2[g];
        for (int c = 0; c < NCH; c++) w3s[g * NCH + c] = w.w3[g * NCH + c] * sc;
    }
    __syncthreads();
    float w10 = w.w1[0], w11 = w.w1[1], w12 = w.w1[2];
    for (int o = tid; o < NF; o += 256) {
        float m[NCH];
#pragma unroll
        for (int c = 0; c < NCH; c++) m[c] = 0.f;
        for (int g = 0; g < NEXP; g++) {
            float w4v = w.w4[o * NEXP + g];
#pragma unroll
            for (int c = 0; c < NCH; c++) m[c] += w4v * w3s[g * NCH + c];
        }
        for (int c = 0; c < NCH; c++) {
            float am = (c > 0) ? m[c - 1] : 0.f;
            float ap = (c < NCH - 1) ? m[c + 1] : 0.f;
            d_Meff[(blk * NF + o) * NCH + c] = w10 * ap + w11 * m[c] + w12 * am;
        }
    }
}

// ---------- K2: per-block Meff@x -> LN -> depthwise temporal conv -> LN ----------
template<int K>
__device__ __forceinline__ void block_impl(const float* __restrict__ x, BP bp, int blk,
                                           int b, int rc, float* sm, float* red) {
    const int Kh = K / 2;
    float* xsh  = sm;
    float* rbuf = xsh + NCH * NT;
    float* meff = rbuf + 1008;
    float* w5s  = meff + ROWS_PER * NCH;
    float* g1s  = w5s + ROWS_PER * 75;
    float* b1s  = g1s + NT;
    float* g2s  = b1s + NT;
    float* b2s  = g2s + NT;
    int tid = threadIdx.x;
    int o0 = rc * ROWS_PER;
    bool act = tid < 250;
    int t0 = tid * 4;

    for (int i = tid; i < NCH * NT; i += 256) xsh[i] = x[(size_t)b * NCH * NT + i];
    for (int i = tid; i < ROWS_PER * NCH; i += 256) meff[i] = d_Meff[(blk * NF + o0) * NCH + i];
    for (int i = tid; i < ROWS_PER * K; i += 256) w5s[i] = bp.w5[o0 * K + i];
    for (int i = tid; i < NT; i += 256) {
        g1s[i] = bp.g1[i]; b1s[i] = bp.b1[i];
        g2s[i] = bp.g2[i]; b2s[i] = bp.b2[i];
    }
    __syncthreads();

    for (int oo = 0; oo < ROWS_PER; oo++) {
        float h0 = 0.f, h1 = 0.f, h2 = 0.f, h3 = 0.f;
        float s1 = 0.f, s2 = 0.f;
        if (act) {
            const float* mrow = meff + oo * NCH;
#pragma unroll
            for (int c = 0; c < NCH; c++) {
                float m = mrow[c];
                float4 xv = *reinterpret_cast<const float4*>(xsh + c * NT + t0);
                h0 += m * xv.x; h1 += m * xv.y; h2 += m * xv.z; h3 += m * xv.w;
            }
            s1 = h0 + h1 + h2 + h3;
            s2 = h0 * h0 + h1 * h1 + h2 * h2 + h3 * h3;
        }
        float2 r = blk_reduce2<8>(s1, s2, red);
        float mean = r.x * (1.0f / NT);
        float rstd = rsqrtf(r.y * (1.0f / NT) - mean * mean + 1e-5f);
        if (act) {
            float4 rv;
            rv.x = (h0 - mean) * rstd * g1s[t0 + 0] + b1s[t0 + 0];
            rv.y = (h1 - mean) * rstd * g1s[t0 + 1] + b1s[t0 + 1];
            rv.z = (h2 - mean) * rstd * g1s[t0 + 2] + b1s[t0 + 2];
            rv.w = (h3 - mean) * rstd * g1s[t0 + 3] + b1s[t0 + 3];
            *reinterpret_cast<float4*>(rbuf + t0) = rv;
        }
        __syncthreads();
        float c0 = 0.f, c1 = 0.f, c2 = 0.f, c3 = 0.f;
        s1 = 0.f; s2 = 0.f;
        if (act) {
            const float* wrow = w5s + oo * K;
            int i0 = t0 - Kh;
            float w0 = (i0 + 0 >= 0) ? rbuf[i0 + 0] : 0.f;
            float w1 = (i0 + 1 >= 0) ? rbuf[i0 + 1] : 0.f;
            float w2 = (i0 + 2 >= 0) ? rbuf[i0 + 2] : 0.f;
            float w3 = (i0 + 3 >= 0) ? rbuf[i0 + 3] : 0.f;
#pragma unroll
            for (int k = 0; k < K; k++) {
                float tap = wrow[k];
                c0 += tap * w0; c1 += tap * w1; c2 += tap * w2; c3 += tap * w3;
                w0 = w1; w1 = w2; w2 = w3;
                int tn = t0 + 4 + k - Kh;
                w3 = (tn >= 0 && tn < NT) ? rbuf[tn] : 0.f;
            }
            s1 = c0 + c1 + c2 + c3;
            s2 = c0 * c0 + c1 * c1 + c2 * c2 + c3 * c3;
        }
        float2 r2 = blk_reduce2<8>(s1, s2, red);
        float m2 = r2.x * (1.0f / NT);
        float rs2 = rsqrtf(r2.y * (1.0f / NT) - m2 * m2 + 1e-5f);
        float* outp = d_H + ((size_t)(b * 450 + blk * NF + o0 + oo)) * NT;
        if (act) {
            float4 ov;
            ov.x = (c0 - m2) * rs2 * g2s[t0 + 0] + b2s[t0 + 0];
            ov.y = (c1 - m2) * rs2 * g2s[t0 + 1] + b2s[t0 + 1];
            ov.z = (c2 - m2) * rs2 * g2s[t0 + 2] + b2s[t0 + 2];
            ov.w = (c3 - m2) * rs2 * g2s[t0 + 3] + b2s[t0 + 3];
            *reinterpret_cast<float4*>(outp + t0) = ov;
        }
    }
}

__global__ void k_block(const float* __restrict__ x, BPs bps) {
    int b = blockIdx.x, blk = blockIdx.y, rc = blockIdx.z;
    extern __shared__ float sm[];
    __shared__ float red[64];
    if (blk == 0)      block_impl<15>(x, bps.p[0], 0, b, rc, sm, red);
    else if (blk == 1) block_impl<75>(x, bps.p[1], 1, b, rc, sm, red);
    else               block_impl<55>(x, bps.p[2], 2, b, rc, sm, red);
}

// ---------- K3: spatial conv 450->100 + center over time ----------
__global__ void k_sconv(const float* __restrict__ wsc) {
    int b = blockIdx.x, s0 = blockIdx.y * SROWS;
    __shared__ float ws[SROWS * 450];
    __shared__ float red[64];
    int tid = threadIdx.x;
    for (int i = tid; i < SROWS * 450; i += 256) ws[i] = wsc[s0 * 450 + i];
    __syncthreads();
    const float* Hb = d_H + (size_t)b * 450 * NT;
    float acc[SROWS][4];
#pragma unroll
    for (int r = 0; r < SROWS; r++)
#pragma unroll
        for (int j = 0; j < 4; j++) acc[r][j] = 0.f;
    for (int i = 0; i < 450; i++) {
        const float* hp = Hb + (size_t)i * NT;
        float hv[4];
#pragma unroll
        for (int j = 0; j < 4; j++) {
            int t = tid + 256 * j;
            hv[j] = (t < NT) ? hp[t] : 0.f;
        }
#pragma unroll
        for (int r = 0; r < SROWS; r++) {
            float w = ws[r * 450 + i];
#pragma unroll
            for (int j = 0; j < 4; j++) acc[r][j] += w * hv[j];
        }
    }
#pragma unroll
    for (int r = 0; r < SROWS; r++) {
        float s = 0.f;
#pragma unroll
        for (int j = 0; j < 4; j++) { int t = tid + 256 * j; if (t < NT) s += acc[r][j]; }
        s = blk_reduce<8>(s, red);
        float mean = s * (1.0f / NT);
        float* op = d_SC + ((size_t)(b * NS + s0 + r)) * NT;
#pragma unroll
        for (int j = 0; j < 4; j++) {
            int t = tid + 256 * j;
            if (t < NT) op[t] = acc[r][j] - mean;
        }
    }
}

// ---------- K4: partial covariance ----------
__global__ void k_covp() {
    int b = blockIdx.x, ch = blockIdx.y;
    __shared__ float sh[NS * 28];
    int tid = threadIdx.x, tx = tid & 15, ty = tid >> 4;
    float acc[7][7];
#pragma unroll
    for (int a = 0; a < 7; a++)
#pragma unroll
        for (int c = 0; c < 7; c++) acc[a][c] = 0.f;
    int tbase0 = ch * 125;
    for (int cc = 0; cc < 5; cc++) {
        int tb = tbase0 + cc * 25;
        __syncthreads();
        for (int idx = tid; idx < NS * 25; idx += 256) {
            int i = idx / 25, tt = idx - i * 25;
            sh[i * 28 + tt] = d_SC[((size_t)(b * NS + i)) * NT + tb + tt];
        }
        __syncthreads();
        for (int tt = 0; tt < 25; tt++) {
            float ai[7], aj[7];
#pragma unroll
            for (int a = 0; a < 7; a++) { int i = ty + 16 * a; ai[a] = (i < NS) ? sh[i * 28 + tt] : 0.f; }
#pragma unroll
            for (int c = 0; c < 7; c++) { int j = tx + 16 * c; aj[c] = (j < NS) ? sh[j * 28 + tt] : 0.f; }
#pragma unroll
            for (int a = 0; a < 7; a++)
#pragma unroll
                for (int c = 0; c < 7; c++) acc[a][c] += ai[a] * aj[c];
        }
    }
#pragma unroll
    for (int a = 0; a < 7; a++)
#pragma unroll
        for (int c = 0; c < 7; c++) {
            int i = ty + 16 * a, j = tx + 16 * c;
            if (i < NS && j < NS)
                d_covp[((size_t)(b * 8 + ch) * NS + i) * NS + j] = acc[a][c];
        }
}

// ---------- K5: cov reduce + ridge + P = W cov W^T ----------
__global__ void k_affine(const float* __restrict__ waff) {
    int b = blockIdx.x;
    extern __shared__ float sm[];
    float* covs = sm;
    float* Ws = covs + NS * PIT;
    float* Ts = Ws + NS * PIT;
    int tid = threadIdx.x, tx = tid & 15, ty = tid >> 4;
    for (int idx = tid; idx < NS * NS; idx += 256) {
        int i = idx / NS, j = idx - i * NS;
        const float* pp = d_covp + (size_t)b * 8 * NS * NS + idx;
        float v = 0.f;
#pragma unroll
        for (int c = 0; c < 8; c++) v += pp[(size_t)c * NS * NS];
        v *= (1.0f / 999.0f);
        if (i == j) v += 1e-4f;
        covs[i * PIT + j] = v;
        Ws[i * PIT + j] = waff[idx];
    }
    __syncthreads();
    float acc[7][7];
#pragma unroll
    for (int a = 0; a < 7; a++)
#pragma unroll
        for (int c = 0; c < 7; c++) acc[a][c] = 0.f;
    for (int k = 0; k < NS; k++) {
        float wa[7], cb[7];
#pragma unroll
        for (int a = 0; a < 7; a++) { int i = ty + 16 * a; wa[a] = (i < NS) ? Ws[i * PIT + k] : 0.f; }
#pragma unroll
        for (int c = 0; c < 7; c++) { int j = tx + 16 * c; cb[c] = (j < NS) ? covs[k * PIT + j] : 0.f; }
#pragma unroll
        for (int a = 0; a < 7; a++)
#pragma unroll
            for (int c = 0; c < 7; c++) acc[a][c] += wa[a] * cb[c];
    }
#pragma unroll
    for (int a = 0; a < 7; a++)
#pragma unroll
        for (int c = 0; c < 7; c++) {
            int i = ty + 16 * a, j = tx + 16 * c;
            if (i < NS && j < NS) Ts[i * PIT + j] = acc[a][c];
        }
    __syncthreads();
#pragma unroll
    for (int a = 0; a < 7; a++)
#pragma unroll
        for (int c = 0; c < 7; c++) acc[a][c] = 0.f;
    for (int k = 0; k < NS; k++) {
        float ta[7], wb[7];
#pragma unroll
        for (int a = 0; a < 7; a++) { int i = ty + 16 * a; ta[a] = (i < NS) ? Ts[i * PIT + k] : 0.f; }
#pragma unroll
        for (int c = 0; c < 7; c++) { int j = tx + 16 * c; wb[c] = (j < NS) ? Ws[j * PIT + k] : 0.f; }
#pragma unroll
        for (int a = 0; a < 7; a++)
#pragma unroll
            for (int c = 0; c < 7; c++) acc[a][c] += ta[a] * wb[c];
    }
#pragma unroll
    for (int a = 0; a < 7; a++)
#pragma unroll
        for (int c = 0; c < 7; c++) {
            int i = ty + 16 * a, j = tx + 16 * c;
            if (i < NS && j < NS) d_P[(size_t)b * NS * NS + i * NS + j] = acc[a][c];
        }
}

// ---------- K6a: Jacobi on A; register-resident indices; rotations logged ----------
__global__ void __launch_bounds__(512, 1)
k_eigA() {
    int b = blockIdx.x;
    extern __shared__ float sm[];
    float* As = sm;                                  // 100*101
    float2* par = (float2*)(As + NS * PIT);          // 50 float2
    __shared__ float red[64];
    int tid = threadIdx.x;
    const float* Pb = d_P + (size_t)b * NS * NS;
    for (int idx = tid; idx < NS * NS; idx += 512) {
        int i = idx / NS, j = idx - i * NS;
        As[i * PIT + j] = 0.5f * (Pb[i * NS + j] + Pb[j * NS + i]);
    }

    // static tri-block ownership: up to 3 (a,bb) blocks per thread
    int ta_[3], tb_[3];
    int nblk = 0;
#pragma unroll
    for (int t = 0; t < 3; t++) {
        int idx = tid + 512 * t;
        ta_[t] = 0; tb_[t] = 0;
        if (idx < 1275) {
            int a = 0, base = 0;
#pragma unroll 1
            for (int it = 0; it < 50; it++) {
                if (base + (50 - a) <= idx) { base += 50 - a; a++; } else break;
            }
            ta_[t] = a; tb_[t] = a + (idx - base);
            nblk = t + 1;
        }
    }
    __syncthreads();

    int nr = 0;
    for (int sweep = 0; sweep < MAXSW; sweep++) {
        float o2 = 0.f, d2 = 0.f;
        for (int idx = tid; idx < NS * NS; idx += 512) {
            int i = idx / NS, j = idx - i * NS;
            float v = As[i * PIT + j];
            if (i == j) d2 += v * v; else o2 += v * v;
        }
        float2 r = blk_reduce2<16>(o2, d2, red);
        if (r.x <= 2e-10f * r.y) break;

        // per-sweep reset of register-resident pair indices (rnd=0 state)
        int pa_[3], qa_[3], pb_[3], qb_[3];
#pragma unroll
        for (int t = 0; t < 3; t++) {
            int a = ta_[t], bb = tb_[t];
            pa_[t] = a;  qa_[t] = (a == 0) ? 99 : 99 - a;
            pb_[t] = bb; qb_[t] = (bb == 0) ? 99 : 99 - bb;
        }
        int pp = tid, qq = (tid == 0) ? 99 : 99 - tid;   // param thread (tid<50)

        for (int rnd = 0; rnd < 99; rnd++) {
            if (tid < 50) {
                float apq = As[pp * PIT + qq];
                float app = As[pp * PIT + pp], aqq = As[qq * PIT + qq];
                float c = 1.0f, s = 0.0f;
                if (fabsf(apq) > 1e-8f * sqrtf(fabsf(app * aqq)) + 1e-38f) {
                    float tau = (aqq - app) / (2.0f * apq);
                    float t = 1.0f / (fabsf(tau) + sqrtf(1.0f + tau * tau));
                    if (tau < 0.f) t = -t;
                    c = rsqrtf(1.0f + t * t);
                    s = t * c;
                }
                float2 cs = make_float2(c, s);
                par[tid] = cs;
                d_rot[b][nr][tid] = cs;
            }
            __syncthreads();
#pragma unroll
            for (int t = 0; t < 3; t++) {
                if (t < nblk) {
                    float2 Pa = par[ta_[t]], Pbv = par[tb_[t]];
                    if (Pa.y != 0.f || Pbv.y != 0.f) {
                        int pa = pa_[t], qa = qa_[t], pb = pb_[t], qb = qb_[t];
                        float ca = Pa.x, sa = Pa.y, cb = Pbv.x, sb = Pbv.y;
                        float x00 = As[pa * PIT + pb], x01 = As[pa * PIT + qb];
                        float x10 = As[qa * PIT + pb], x11 = As[qa * PIT + qb];
                        float y00 = cb * x00 - sb * x01, y01 = sb * x00 + cb * x01;
                        float y10 = cb * x10 - sb * x11, y11 = sb * x10 + cb * x11;
                        float z00 = ca * y00 - sa * y10, z10 = sa * y00 + ca * y10;
                        float z01 = ca * y01 - sa * y11, z11 = sa * y01 + ca * y11;
                        As[pa * PIT + pb] = z00; As[pa * PIT + qb] = z01;
                        As[qa * PIT + pb] = z10; As[qa * PIT + qb] = z11;
                        if (ta_[t] != tb_[t]) {
                            As[pb * PIT + pa] = z00; As[qb * PIT + pa] = z01;
                            As[pb * PIT + qa] = z10; As[qb * PIT + qa] = z11;
                        }
                    }
                }
            }
            // increment register indices: p always ++%99; q ++%99 unless pinned at 99
#pragma unroll
            for (int t = 0; t < 3; t++) {
                pa_[t]++; if (pa_[t] >= 99) pa_[t] = 0;
                if (qa_[t] != 99) { qa_[t]++; if (qa_[t] >= 99) qa_[t] = 0; }
                pb_[t]++; if (pb_[t] >= 99) pb_[t] = 0;
                if (qb_[t] != 99) { qb_[t]++; if (qb_[t] >= 99) qb_[t] = 0; }
            }
            pp++; if (pp >= 99) pp = 0;
            if (qq != 99) { qq++; if (qq >= 99) qq = 0; }
            nr++;
            __syncthreads();
        }
    }
    if (tid == 0) d_nr[b] = nr;
    if (tid < NS) d_eval[b][tid] = As[tid * PIT + tid];
}

// ---------- K6b: replay rotation log onto V (10 rows per CTA) ----------
__global__ void __launch_bounds__(256, 1)
k_vrep() {
    int b = blockIdx.x, ch = blockIdx.y;
    int r0 = ch * VROWS;
    __shared__ float Vr[VROWS * PIT];
    __shared__ float2 pbuf[2][50];
    int tid = threadIdx.x;
    for (int idx = tid; idx < VROWS * NS; idx += 256) {
        int i = idx / NS, j = idx - i * NS;
        Vr[i * PIT + j] = (r0 + i == j) ? 1.0f : 0.0f;
    }
    int nr = d_nr[b];
    if (tid < 50 && nr > 0) pbuf[0][tid] = d_rot[b][0][tid];
    __syncthreads();

    int rt = 0;
    for (int rnd = 0; rnd < nr; rnd++) {
        int buf = rnd & 1;
        float2 nxt = make_float2(1.f, 0.f);
        bool pf = (tid < 50) && (rnd + 1 < nr);
        if (pf) nxt = d_rot[b][rnd + 1][tid];
#pragma unroll 2
        for (int idx = tid; idx < VROWS * 50; idx += 256) {
            int i = idx / 50, k = idx - i * 50;
            float2 cs = pbuf[buf][k];
            if (cs.y != 0.f) {
                int p, q;
                if (k == 0) { p = rt; q = 99; }
                else {
                    p = rt + k;       if (p >= 99) p -= 99;
                    q = rt + 99 - k;  if (q >= 99) q -= 99;
                }
                float xp = Vr[i * PIT + p], xq = Vr[i * PIT + q];
                Vr[i * PIT + p] = cs.x * xp - cs.y * xq;
                Vr[i * PIT + q] = cs.y * xp + cs.x * xq;
            }
        }
        if (pf) pbuf[buf ^ 1][tid] = nxt;
        rt++; if (rt >= 99) rt = 0;
        __syncthreads();
    }
    for (int idx = tid; idx < VROWS * NS; idx += 256) {
        int i = idx / NS, j = idx - i * NS;
        d_V[b][r0 + i][j] = Vr[i * PIT + j];
    }
}

// ---------- K6c: epilogue logm triu + FC ----------
__global__ void __launch_bounds__(1024, 1)
k_epi(const float* __restrict__ wfc, const float* __restrict__ bfc,
      float* __restrict__ out) {
    int b = blockIdx.x;
    extern __shared__ float sm[];
    float* As = sm;
    float* Vs = As + NS * PIT;
    __shared__ float red[64];
    __shared__ float llog[NS];
    int tid = threadIdx.x;
    if (tid < NS) llog[tid] = logf(fmaxf(d_eval[b][tid], 1e-6f));
    for (int idx = tid; idx < NS * NS; idx += 1024) {
        int i = idx / NS, k = idx - i * NS;
        Vs[i * PIT + k] = d_V[b][i][k];
    }
    __syncthreads();
    for (int idx = tid; idx < NS * NS; idx += 1024) {
        int i = idx / NS, k = idx - i * NS;
        As[i * PIT + k] = Vs[i * PIT + k] * llog[k];
    }
    __syncthreads();

    float l0 = 0.f, l1 = 0.f, l2 = 0.f, l3 = 0.f;
    float* flat = out + 64 + (size_t)b * 5050;
    for (int idx = tid; idx < 5050; idx += 1024) {
        int i = (int)((201.0f - sqrtf(201.0f * 201.0f - 8.0f * (float)idx)) * 0.5f);
        if (i < 0) i = 0; if (i > 99) i = 99;
        while (i > 0 && i * (201 - i) / 2 > idx) i--;
        while (i < 99 && (i + 1) * (200 - i) / 2 <= idx) i++;
        int j = i + (idx - i * (201 - i) / 2);
        float a = 0.f;
        for (int k = 0; k < NS; k++) a += As[i * PIT + k] * Vs[j * PIT + k];
        float v = a * ((i == j) ? 1.0f : 1.41421356237309515f);
        flat[idx] = v;
        l0 += v * wfc[idx];
        l1 += v * wfc[5050 + idx];
        l2 += v * wfc[2 * 5050 + idx];
        l3 += v * wfc[3 * 5050 + idx];
    }
    l0 = blk_reduce<32>(l0, red);
    l1 = blk_reduce<32>(l1, red);
    l2 = blk_reduce<32>(l2, red);
    l3 = blk_reduce<32>(l3, red);
    if (tid == 0) {
        out[b * 4 + 0] = l0 + bfc[0];
        out[b * 4 + 1] = l1 + bfc[1];
        out[b * 4 + 2] = l2 + bfc[2];
        out[b * 4 + 3] = l3 + bfc[3];
    }
}

// ---------- launch ----------
extern "C" void kernel_launch(void* const* d_in, const int* in_sizes, int n_in,
                              void* d_out, int out_size) {
    const float* x = (const float*)d_in[0];
    PrepPs pps; BPs bps;
    for (int bi = 0; bi < 3; bi++) {
        int base = 1 + bi * 9;
        pps.p[bi].w1 = (const float*)d_in[base + 0];
        pps.p[bi].w2 = (const float*)d_in[base + 1];
        pps.p[bi].w3 = (const float*)d_in[base + 2];
        pps.p[bi].w4 = (const float*)d_in[base + 3];
        bps.p[bi].g1 = (const float*)d_in[base + 4];
        bps.p[bi].b1 = (const float*)d_in[base + 5];
        bps.p[bi].w5 = (const float*)d_in[base + 6];
        bps.p[bi].g2 = (const float*)d_in[base + 7];
        bps.p[bi].b2 = (const float*)d_in[base + 8];
    }
    const float* wsc  = (const float*)d_in[28];
    const float* waff = (const float*)d_in[29];
    const float* wfc  = (const float*)d_in[30];
    const float* bfc  = (const float*)d_in[31];

    const int SMEM_BLOCK = (NCH * NT + 1008 + ROWS_PER * NCH + ROWS_PER * 75 + 4 * NT) * 4;
    const int SMEM_AFF = 3 * NS * PIT * 4;
    const int SMEM_A   = NS * PIT * 4 + 50 * 8;
    const int SMEM_EPI = 2 * NS * PIT * 4;
    cudaFuncSetAttribute(k_block, cudaFuncAttributeMaxDynamicSharedMemorySize, SMEM_BLOCK);
    cudaFuncSetAttribute(k_affine, cudaFuncAttributeMaxDynamicSharedMemorySize, SMEM_AFF);
    cudaFuncSetAttribute(k_eigA, cudaFuncAttributeMaxDynamicSharedMemorySize, SMEM_A);
    cudaFuncSetAttribute(k_epi, cudaFuncAttributeMaxDynamicSharedMemorySize, SMEM_EPI);

    k_prep<<<3, 256>>>(pps);
    k_block<<<dim3(NB, 3, 5), 256, SMEM_BLOCK>>>(x, bps);
    k_sconv<<<dim3(NB, 10), 256>>>(wsc);
    k_covp<<<dim3(NB, 8), 256>>>();
    k_affine<<<NB, 256, SMEM_AFF>>>(waff);
    k_eigA<<<NB, 512, SMEM_A>>>();
    k_vrep<<<dim3(NB, 10), 256>>>();
    k_epi<<<NB, 1024, SMEM_EPI>>>(wfc, bfc, (float*)d_out);
}